// round 1
// baseline (speedup 1.0000x reference)
#include <cuda_runtime.h>
#include <math.h>

#define D_MODEL 1024
#define N_HEADS 16
#define HEAD_DIM 64
#define BATCH 4
#define SEQ 2048
#define M_ROWS (BATCH * SEQ)   // 8192

// ---------------------------------------------------------------------------
// Scratch (device globals: no allocation allowed in kernel_launch)
// ---------------------------------------------------------------------------
__device__ float g_q[BATCH * N_HEADS * SEQ * HEAD_DIM];    // [B,H,S,Dh]
__device__ float g_k[BATCH * N_HEADS * SEQ * HEAD_DIM];
__device__ float g_v[BATCH * N_HEADS * SEQ * HEAD_DIM];
__device__ float g_attn[M_ROWS * D_MODEL];                 // [B,S,D]

// ---------------------------------------------------------------------------
// GEMM:  Y = X @ W^T + bias
//   X: [M_ROWS, D_MODEL] row-major, W: [D_MODEL, D_MODEL] row-major
//   HEAD_SPLIT=1: write Y[m,n] to [B,H,S,Dh] layout (for Q/K/V)
//   HEAD_SPLIT=0: write Y[m,n] row-major (final projection)
// 64x64 block tile, K-step 16, 4x4 per-thread micro-tile, 256 threads.
// ---------------------------------------------------------------------------
template <int HEAD_SPLIT>
__global__ void __launch_bounds__(256) gemm_bias_kernel(
    const float* __restrict__ X, const float* __restrict__ W,
    const float* __restrict__ bias, float* __restrict__ Y)
{
    __shared__ float As[16][64];   // As[k][m]
    __shared__ float Bs[16][64];   // Bs[k][n]

    const int tid = threadIdx.x;
    const int tx = tid & 15;       // 0..15 -> n
    const int ty = tid >> 4;       // 0..15 -> m
    const int m0 = blockIdx.y << 6;
    const int n0 = blockIdx.x << 6;

    float acc[4][4];
#pragma unroll
    for (int i = 0; i < 4; i++)
#pragma unroll
        for (int j = 0; j < 4; j++) acc[i][j] = 0.0f;

    for (int k0 = 0; k0 < D_MODEL; k0 += 16) {
#pragma unroll
        for (int i = 0; i < 4; i++) {
            int idx = tid + (i << 8);          // 0..1023
            int mm = idx >> 4;                 // 0..63
            int kk = idx & 15;                 // 0..15
            As[kk][mm] = X[(m0 + mm) * D_MODEL + k0 + kk];
            Bs[kk][mm] = W[(n0 + mm) * D_MODEL + k0 + kk];
        }
        __syncthreads();

#pragma unroll
        for (int kk = 0; kk < 16; kk++) {
            float4 a4 = *(const float4*)&As[kk][ty << 2];
            float4 b4 = *(const float4*)&Bs[kk][tx << 2];
            float av[4] = {a4.x, a4.y, a4.z, a4.w};
            float bv[4] = {b4.x, b4.y, b4.z, b4.w};
#pragma unroll
            for (int i = 0; i < 4; i++)
#pragma unroll
                for (int j = 0; j < 4; j++)
                    acc[i][j] += av[i] * bv[j];
        }
        __syncthreads();
    }

#pragma unroll
    for (int i = 0; i < 4; i++) {
        int m = m0 + (ty << 2) + i;
#pragma unroll
        for (int j = 0; j < 4; j++) {
            int n = n0 + (tx << 2) + j;
            float v = acc[i][j] + bias[n];
            if (HEAD_SPLIT) {
                int b = m / SEQ;
                int s = m - b * SEQ;
                int h = n >> 6;                // n / HEAD_DIM
                int dh = n & 63;
                g_dummy_noop: ;
                ((float*)Y)[((b * N_HEADS + h) * SEQ + s) * HEAD_DIM + dh] = v;
            } else {
                Y[m * D_MODEL + n] = v;
            }
        }
    }
}

// ---------------------------------------------------------------------------
// Flash attention: one CTA per (b, h, 64 query rows).
//   scores = (Q*scale) @ K^T, mask==0 -> -1e9, online softmax, O += P @ V.
// Output written to [B, S, H*Dh] (== [B,S,D]) so the final GEMM reads it flat.
// ---------------------------------------------------------------------------
#define KPAD 68
#define ATTN_SMEM_FLOATS (4 * 64 * KPAD + 128)
#define ATTN_SMEM_BYTES (ATTN_SMEM_FLOATS * 4)

__global__ void __launch_bounds__(256) attn_kernel(const int* __restrict__ mask,
                                                   float* __restrict__ out)
{
    extern __shared__ float sm[];
    float* Qs = sm;                        // 64 x KPAD (pre-scaled)
    float* Ks = Qs + 64 * KPAD;            // 64 x KPAD
    float* Vs = Ks + 64 * KPAD;            // 64 x KPAD
    float* Ps = Vs + 64 * KPAD;            // 64 x KPAD (scores -> probs)
    float* s_alpha = Ps + 64 * KPAD;       // 64
    float* s_linv  = s_alpha + 64;         // 64

    const int tid = threadIdx.x;
    const int bh = blockIdx.y;             // 0..63
    const int b = bh >> 4;
    const int h = bh & 15;
    const int q0 = blockIdx.x << 6;

    const float* Q = g_q + bh * SEQ * HEAD_DIM;
    const float* K = g_k + bh * SEQ * HEAD_DIM;
    const float* V = g_v + bh * SEQ * HEAD_DIM;

    const int rblk = tid >> 4;             // 0..15 -> 4 q-rows
    const int cblk = tid & 15;             // 0..15 -> 4 cols

    const float scale = 0.125f;            // 1/sqrt(64)
    for (int i = tid; i < 64 * HEAD_DIM; i += 256) {
        int r = i >> 6, d = i & 63;
        Qs[r * KPAD + d] = Q[(q0 + r) * HEAD_DIM + d] * scale;
    }

    float o[4][4];
#pragma unroll
    for (int i = 0; i < 4; i++)
#pragma unroll
        for (int j = 0; j < 4; j++) o[i][j] = 0.0f;

    float m_r = -1e30f;   // valid only for tid < 64 (row = tid)
    float l_r = 0.0f;

    for (int kt = 0; kt < SEQ / 64; kt++) {
        __syncthreads();   // previous iteration done with Ks/Vs/Ps (and Qs visible)
        for (int i = tid; i < 64 * HEAD_DIM; i += 256) {
            int r = i >> 6, d = i & 63;
            Ks[r * KPAD + d] = K[(kt * 64 + r) * HEAD_DIM + d];
            Vs[r * KPAD + d] = V[(kt * 64 + r) * HEAD_DIM + d];
        }
        __syncthreads();

        // ---- scores: S[64x64] = Qs @ Ks^T ----
        float s[4][4];
#pragma unroll
        for (int i = 0; i < 4; i++)
#pragma unroll
            for (int j = 0; j < 4; j++) s[i][j] = 0.0f;

        for (int d = 0; d < HEAD_DIM; d++) {
            float av[4], bv[4];
#pragma unroll
            for (int i = 0; i < 4; i++) av[i] = Qs[((rblk << 2) + i) * KPAD + d];
#pragma unroll
            for (int j = 0; j < 4; j++) bv[j] = Ks[((cblk << 2) + j) * KPAD + d];
#pragma unroll
            for (int i = 0; i < 4; i++)
#pragma unroll
                for (int j = 0; j < 4; j++)
                    s[i][j] += av[i] * bv[j];
        }
#pragma unroll
        for (int i = 0; i < 4; i++)
#pragma unroll
            for (int j = 0; j < 4; j++)
                Ps[((rblk << 2) + i) * KPAD + (cblk << 2) + j] = s[i][j];
        __syncthreads();

        // ---- masked online softmax: one thread per row ----
        if (tid < 64) {
            const int* mrow = mask + (b * SEQ + q0 + tid) * SEQ + kt * 64;
            float* prow = Ps + tid * KPAD;
            float mx = m_r;
            for (int j = 0; j < 64; j++) {
                float sv = prow[j];
                if (mrow[j] == 0) sv = -1e9f;
                prow[j] = sv;
                mx = fmaxf(mx, sv);
            }
            float alpha = __expf(m_r - mx);
            float sum = 0.0f;
            for (int j = 0; j < 64; j++) {
                float p = __expf(prow[j] - mx);
                prow[j] = p;
                sum += p;
            }
            m_r = mx;
            l_r = l_r * alpha + sum;
            s_alpha[tid] = alpha;
        }
        __syncthreads();

        // ---- O = O * alpha + P @ V ----
#pragma unroll
        for (int i = 0; i < 4; i++) {
            float alpha = s_alpha[(rblk << 2) + i];
#pragma unroll
            for (int j = 0; j < 4; j++) o[i][j] *= alpha;
        }
        for (int jk = 0; jk < 64; jk++) {
            float4 v4 = *(const float4*)&Vs[jk * KPAD + (cblk << 2)];
            float vv[4] = {v4.x, v4.y, v4.z, v4.w};
#pragma unroll
            for (int i = 0; i < 4; i++) {
                float p = Ps[((rblk << 2) + i) * KPAD + jk];
#pragma unroll
                for (int j = 0; j < 4; j++)
                    o[i][j] += p * vv[j];
            }
        }
    }

    if (tid < 64) s_linv[tid] = 1.0f / l_r;
    __syncthreads();

#pragma unroll
    for (int i = 0; i < 4; i++) {
        int r = (rblk << 2) + i;
        float inv = s_linv[r];
        int row = b * SEQ + q0 + r;
#pragma unroll
        for (int j = 0; j < 4; j++)
            out[row * D_MODEL + h * HEAD_DIM + (cblk << 2) + j] = o[i][j] * inv;
    }
}

// ---------------------------------------------------------------------------
// Launch
// ---------------------------------------------------------------------------
extern "C" void kernel_launch(void* const* d_in, const int* in_sizes, int n_in,
                              void* d_out, int out_size)
{
    const float* query  = (const float*)d_in[0];
    const float* key_in = (const float*)d_in[1];
    const float* value  = (const float*)d_in[2];
    const int*   mask   = (const int*)d_in[3];
    const float* wq_w   = (const float*)d_in[4];
    const float* wq_b   = (const float*)d_in[5];
    const float* wk_w   = (const float*)d_in[6];
    const float* wk_b   = (const float*)d_in[7];
    const float* wv_w   = (const float*)d_in[8];
    const float* wv_b   = (const float*)d_in[9];
    const float* fc_w   = (const float*)d_in[10];
    const float* fc_b   = (const float*)d_in[11];
    float* out = (float*)d_out;

    float *pq, *pk, *pv, *pattn;
    cudaGetSymbolAddress((void**)&pq, g_q);
    cudaGetSymbolAddress((void**)&pk, g_k);
    cudaGetSymbolAddress((void**)&pv, g_v);
    cudaGetSymbolAddress((void**)&pattn, g_attn);

    cudaFuncSetAttribute(attn_kernel,
                         cudaFuncAttributeMaxDynamicSharedMemorySize,
                         ATTN_SMEM_BYTES);

    dim3 gemm_grid(D_MODEL / 64, M_ROWS / 64);   // (16, 128)
    gemm_bias_kernel<1><<<gemm_grid, 256>>>(query,  wq_w, wq_b, pq);
    gemm_bias_kernel<1><<<gemm_grid, 256>>>(key_in, wk_w, wk_b, pk);
    gemm_bias_kernel<1><<<gemm_grid, 256>>>(value,  wv_w, wv_b, pv);

    dim3 attn_grid(SEQ / 64, BATCH * N_HEADS);   // (32, 64)
    attn_kernel<<<attn_grid, 256, ATTN_SMEM_BYTES>>>(mask, pattn);

    gemm_bias_kernel<0><<<gemm_grid, 256>>>(pattn, fc_w, fc_b, out);
}

// round 2
// speedup vs baseline: 4.7770x; 4.7770x over previous
#include <cuda_runtime.h>
#include <stdint.h>

#define D_MODEL 1024
#define N_HEADS 16
#define HEAD_DIM 64
#define BATCH 4
#define SEQ 2048
#define M_ROWS (BATCH * SEQ)   // 8192

// ---------------------------------------------------------------------------
// Scratch (device globals: no allocation allowed)
// ---------------------------------------------------------------------------
__device__ float g_q[BATCH * N_HEADS * SEQ * HEAD_DIM];    // [B,H,S,Dh]
__device__ float g_k[BATCH * N_HEADS * SEQ * HEAD_DIM];    // [B,H,S,Dh]
__device__ float g_v[BATCH * N_HEADS * SEQ * HEAD_DIM];    // [B,H,Dh,S]  (transposed!)
__device__ float g_attn[M_ROWS * D_MODEL];                 // [B,S,D]

// ---------------------------------------------------------------------------
// tf32 helpers
// ---------------------------------------------------------------------------
__device__ __forceinline__ uint32_t f2tf(float x) {
    uint32_t r;
    asm("cvt.rna.tf32.f32 %0, %1;" : "=r"(r) : "f"(x));
    return r;
}

__device__ __forceinline__ void mma8(float* c, const uint32_t* a, const uint32_t* b) {
    asm volatile(
        "mma.sync.aligned.m16n8k8.row.col.f32.tf32.tf32.f32 "
        "{%0,%1,%2,%3}, {%4,%5,%6,%7}, {%8,%9}, {%0,%1,%2,%3};"
        : "+f"(c[0]), "+f"(c[1]), "+f"(c[2]), "+f"(c[3])
        : "r"(a[0]), "r"(a[1]), "r"(a[2]), "r"(a[3]), "r"(b[0]), "r"(b[1]));
}

// ---------------------------------------------------------------------------
// GEMM: Y = X @ W^T + bias   (X:[8192,1024], W:[1024,1024], both row-major)
// MODE 0: Y row-major [m][n]
// MODE 1: Y = [B,H,S,Dh]
// MODE 2: Y = [B,H,Dh,S]  (transposed, for V)
// 128x128 tile, K-chunk 32, 8 warps at 64x32, m16n8k8 tf32.
// ---------------------------------------------------------------------------
template <int MODE>
__device__ __forceinline__ void put_out(float* __restrict__ Y, int m, int n, float v) {
    if (MODE == 0) {
        Y[(size_t)m * D_MODEL + n] = v;
    } else {
        int b = m >> 11, s = m & 2047, h = n >> 6, dh = n & 63;
        if (MODE == 1)
            Y[(((size_t)(b * N_HEADS + h)) * SEQ + s) * HEAD_DIM + dh] = v;
        else
            Y[(((size_t)(b * N_HEADS + h)) * HEAD_DIM + dh) * SEQ + s] = v;
    }
}

template <int MODE>
__global__ void __launch_bounds__(256) gemm_tf32(
    const float* __restrict__ X, const float* __restrict__ W,
    const float* __restrict__ bias, float* __restrict__ Y)
{
    __shared__ uint32_t As[128][36];   // [m][k] tf32, stride 36 (==4 mod 32)
    __shared__ uint32_t Bs[128][36];   // [n][k]

    const int tid = threadIdx.x;
    const int l = tid & 31;
    const int wid = tid >> 5;
    const int m0 = blockIdx.y << 7;
    const int n0 = blockIdx.x << 7;
    const int wm = (wid >> 2) << 6;    // 0 / 64
    const int wn = (wid & 3) << 5;     // 0 / 32 / 64 / 96

    float c[4][4][4];
#pragma unroll
    for (int mt = 0; mt < 4; mt++)
#pragma unroll
        for (int nt = 0; nt < 4; nt++)
#pragma unroll
            for (int i = 0; i < 4; i++) c[mt][nt][i] = 0.0f;

    for (int k0 = 0; k0 < D_MODEL; k0 += 32) {
        __syncthreads();
#pragma unroll
        for (int i = 0; i < 4; i++) {
            int idx = tid + (i << 8);
            int row = idx >> 3, q = (idx & 7) << 2;
            float4 xv = *(const float4*)(X + (size_t)(m0 + row) * D_MODEL + k0 + q);
            uint4 ux = {f2tf(xv.x), f2tf(xv.y), f2tf(xv.z), f2tf(xv.w)};
            *(uint4*)&As[row][q] = ux;
            float4 wv = *(const float4*)(W + (size_t)(n0 + row) * D_MODEL + k0 + q);
            uint4 uw = {f2tf(wv.x), f2tf(wv.y), f2tf(wv.z), f2tf(wv.w)};
            *(uint4*)&Bs[row][q] = uw;
        }
        __syncthreads();

#pragma unroll
        for (int ks = 0; ks < 4; ks++) {
            int kk = ks << 3;
            uint32_t a[4][4], b[4][2];
#pragma unroll
            for (int mt = 0; mt < 4; mt++) {
                int r = wm + (mt << 4) + (l >> 2);
                a[mt][0] = As[r][kk + (l & 3)];
                a[mt][1] = As[r + 8][kk + (l & 3)];
                a[mt][2] = As[r][kk + (l & 3) + 4];
                a[mt][3] = As[r + 8][kk + (l & 3) + 4];
            }
#pragma unroll
            for (int nt = 0; nt < 4; nt++) {
                int r = wn + (nt << 3) + (l >> 2);
                b[nt][0] = Bs[r][kk + (l & 3)];
                b[nt][1] = Bs[r][kk + (l & 3) + 4];
            }
#pragma unroll
            for (int mt = 0; mt < 4; mt++)
#pragma unroll
                for (int nt = 0; nt < 4; nt++)
                    mma8(c[mt][nt], a[mt], b[nt]);
        }
    }

#pragma unroll
    for (int mt = 0; mt < 4; mt++) {
#pragma unroll
        for (int nt = 0; nt < 4; nt++) {
            int m = m0 + wm + (mt << 4) + (l >> 2);
            int n = n0 + wn + (nt << 3) + ((l & 3) << 1);
            float b0 = bias[n], b1 = bias[n + 1];
            put_out<MODE>(Y, m,     n,     c[mt][nt][0] + b0);
            put_out<MODE>(Y, m,     n + 1, c[mt][nt][1] + b1);
            put_out<MODE>(Y, m + 8, n,     c[mt][nt][2] + b0);
            put_out<MODE>(Y, m + 8, n + 1, c[mt][nt][3] + b1);
        }
    }
}

// ---------------------------------------------------------------------------
// Flash attention, tf32 mma. One CTA per (bh, 64 q-rows); K-chunk 128.
// ---------------------------------------------------------------------------
#define ATTN_SMEM_BYTES ((64*68 + 128*68 + 64*132 + 64*132 + 128) * 4)

__global__ void __launch_bounds__(256) attn_tf32(const int* __restrict__ mask,
                                                 float* __restrict__ out)
{
    extern __shared__ char smraw[];
    uint32_t* Qs = (uint32_t*)smraw;          // [64][68]  tf32 (pre-scaled)
    uint32_t* Ks = Qs + 64 * 68;              // [128][68] tf32
    uint32_t* Vs = Ks + 128 * 68;             // [64][132] tf32  ([dh][kpos])
    uint32_t* Pu = Vs + 64 * 132;             // [64][132] fp32 scores -> tf32 probs
    float* s_alpha = (float*)(Pu + 64 * 132); // [64]
    float* s_linv  = s_alpha + 64;            // [64]

    const int tid = threadIdx.x;
    const int l = tid & 31;
    const int wid = tid >> 5;
    const int bh = blockIdx.y;
    const int b = bh >> 4, h = bh & 15;
    const int q0 = blockIdx.x << 6;

    const float* Q = g_q + (size_t)bh * SEQ * HEAD_DIM + (size_t)q0 * HEAD_DIM;
    const float* K = g_k + (size_t)bh * SEQ * HEAD_DIM;
    const float* V = g_v + (size_t)bh * HEAD_DIM * SEQ;   // [dh][s]

    // stage Q (scaled by 1/sqrt(64))
#pragma unroll
    for (int i = 0; i < 4; i++) {
        int idx = tid + (i << 8);
        int r = idx >> 4, q = (idx & 15) << 2;
        float4 v = *(const float4*)(Q + r * HEAD_DIM + q);
        uint4 u = {f2tf(v.x * 0.125f), f2tf(v.y * 0.125f),
                   f2tf(v.z * 0.125f), f2tf(v.w * 0.125f)};
        *(uint4*)&Qs[r * 68 + q] = u;
    }

    float o[4][4];
#pragma unroll
    for (int nt = 0; nt < 4; nt++)
#pragma unroll
        for (int i = 0; i < 4; i++) o[nt][i] = 0.0f;

    float m_r = -1e30f, l_r = 0.0f;
    const int srow = tid >> 2, ssub = tid & 3;   // softmax: 4 threads per row
    const int wm = (wid & 3) << 4;               // row offset (both phases)
    const int qn = (wid >> 2) << 6;              // QK col offset: 0 / 64
    const int pn = (wid >> 2) << 5;              // PV  col offset: 0 / 32

    for (int kt = 0; kt < SEQ / 128; kt++) {
        const int k0 = kt << 7;
        __syncthreads();
        // stage K tile [128][64]
#pragma unroll
        for (int i = 0; i < 8; i++) {
            int idx = tid + (i << 8);
            int r = idx >> 4, q = (idx & 15) << 2;
            float4 v = *(const float4*)(K + (size_t)(k0 + r) * HEAD_DIM + q);
            uint4 u = {f2tf(v.x), f2tf(v.y), f2tf(v.z), f2tf(v.w)};
            *(uint4*)&Ks[r * 68 + q] = u;
        }
        // stage V tile [64][128] (dh-major, kpos contiguous)
#pragma unroll
        for (int i = 0; i < 8; i++) {
            int idx = tid + (i << 8);
            int d = idx >> 5, q = (idx & 31) << 2;
            float4 v = *(const float4*)(V + (size_t)d * SEQ + k0 + q);
            uint4 u = {f2tf(v.x), f2tf(v.y), f2tf(v.z), f2tf(v.w)};
            *(uint4*)&Vs[d * 132 + q] = u;
        }
        __syncthreads();

        // ---- QK^T: warp computes rows [wm,wm+16) x cols [qn,qn+64) ----
        {
            float cs[8][4];
#pragma unroll
            for (int nt = 0; nt < 8; nt++)
#pragma unroll
                for (int i = 0; i < 4; i++) cs[nt][i] = 0.0f;

#pragma unroll
            for (int ks = 0; ks < 8; ks++) {
                int kk = ks << 3;
                uint32_t a[4];
                int r = wm + (l >> 2);
                a[0] = Qs[r * 68 + kk + (l & 3)];
                a[1] = Qs[(r + 8) * 68 + kk + (l & 3)];
                a[2] = Qs[r * 68 + kk + (l & 3) + 4];
                a[3] = Qs[(r + 8) * 68 + kk + (l & 3) + 4];
#pragma unroll
                for (int nt = 0; nt < 8; nt++) {
                    uint32_t bb[2];
                    int rn = qn + (nt << 3) + (l >> 2);
                    bb[0] = Ks[rn * 68 + kk + (l & 3)];
                    bb[1] = Ks[rn * 68 + kk + (l & 3) + 4];
                    mma8(cs[nt], a, bb);
                }
            }
#pragma unroll
            for (int nt = 0; nt < 8; nt++) {
                int r = wm + (l >> 2);
                int cc = qn + (nt << 3) + ((l & 3) << 1);
                Pu[r * 132 + cc]           = __float_as_uint(cs[nt][0]);
                Pu[r * 132 + cc + 1]       = __float_as_uint(cs[nt][1]);
                Pu[(r + 8) * 132 + cc]     = __float_as_uint(cs[nt][2]);
                Pu[(r + 8) * 132 + cc + 1] = __float_as_uint(cs[nt][3]);
            }
        }
        __syncthreads();

        // ---- masked online softmax: 4 threads per row, 32 cols each ----
        {
            float sv[32];
            const uint32_t* prow = Pu + srow * 132 + (ssub << 5);
            const int* mrow = mask + ((size_t)(b * SEQ + q0 + srow)) * SEQ + k0 + (ssub << 5);
            float mx = m_r;
#pragma unroll
            for (int j = 0; j < 8; j++) {
                uint4 s4 = *(const uint4*)(prow + (j << 2));
                int4 m4 = *(const int4*)(mrow + (j << 2));
                float v0 = m4.x ? __uint_as_float(s4.x) : -1e9f;
                float v1 = m4.y ? __uint_as_float(s4.y) : -1e9f;
                float v2 = m4.z ? __uint_as_float(s4.z) : -1e9f;
                float v3 = m4.w ? __uint_as_float(s4.w) : -1e9f;
                sv[j * 4 + 0] = v0; sv[j * 4 + 1] = v1;
                sv[j * 4 + 2] = v2; sv[j * 4 + 3] = v3;
                mx = fmaxf(mx, fmaxf(fmaxf(v0, v1), fmaxf(v2, v3)));
            }
            mx = fmaxf(mx, __shfl_xor_sync(0xffffffffu, mx, 1));
            mx = fmaxf(mx, __shfl_xor_sync(0xffffffffu, mx, 2));
            float alpha = __expf(m_r - mx);
            float sum = 0.0f;
            uint32_t* pw = Pu + srow * 132 + (ssub << 5);
#pragma unroll
            for (int j = 0; j < 32; j++) {
                float p = __expf(sv[j] - mx);
                sum += p;
                pw[j] = f2tf(p);
            }
            sum += __shfl_xor_sync(0xffffffffu, sum, 1);
            sum += __shfl_xor_sync(0xffffffffu, sum, 2);
            m_r = mx;
            l_r = l_r * alpha + sum;
            if (ssub == 0) s_alpha[srow] = alpha;
        }
        __syncthreads();

        // ---- PV: warp computes rows [wm,wm+16) x dh [pn,pn+32) ----
        {
            float a0 = s_alpha[wm + (l >> 2)];
            float a1 = s_alpha[wm + (l >> 2) + 8];
#pragma unroll
            for (int nt = 0; nt < 4; nt++) {
                o[nt][0] *= a0; o[nt][1] *= a0;
                o[nt][2] *= a1; o[nt][3] *= a1;
            }
#pragma unroll
            for (int ks = 0; ks < 16; ks++) {
                int kk = ks << 3;
                uint32_t a[4];
                int r = wm + (l >> 2);
                a[0] = Pu[r * 132 + kk + (l & 3)];
                a[1] = Pu[(r + 8) * 132 + kk + (l & 3)];
                a[2] = Pu[r * 132 + kk + (l & 3) + 4];
                a[3] = Pu[(r + 8) * 132 + kk + (l & 3) + 4];
#pragma unroll
                for (int nt = 0; nt < 4; nt++) {
                    uint32_t bb[2];
                    int rd = pn + (nt << 3) + (l >> 2);
                    bb[0] = Vs[rd * 132 + kk + (l & 3)];
                    bb[1] = Vs[rd * 132 + kk + (l & 3) + 4];
                    mma8(o[nt], a, bb);
                }
            }
        }
    }

    if (ssub == 0) s_linv[srow] = 1.0f / l_r;
    __syncthreads();

#pragma unroll
    for (int nt = 0; nt < 4; nt++) {
        int r = wm + (l >> 2);
        int cc = pn + (nt << 3) + ((l & 3) << 1);
        float i0 = s_linv[r], i1 = s_linv[r + 8];
        size_t base0 = (size_t)(b * SEQ + q0 + r) * D_MODEL + h * HEAD_DIM + cc;
        size_t base1 = (size_t)(b * SEQ + q0 + r + 8) * D_MODEL + h * HEAD_DIM + cc;
        out[base0]     = o[nt][0] * i0;
        out[base0 + 1] = o[nt][1] * i0;
        out[base1]     = o[nt][2] * i1;
        out[base1 + 1] = o[nt][3] * i1;
    }
}

// ---------------------------------------------------------------------------
// Launch
// ---------------------------------------------------------------------------
extern "C" void kernel_launch(void* const* d_in, const int* in_sizes, int n_in,
                              void* d_out, int out_size)
{
    const float* query  = (const float*)d_in[0];
    const float* key_in = (const float*)d_in[1];
    const float* value  = (const float*)d_in[2];
    const int*   mask   = (const int*)d_in[3];
    const float* wq_w   = (const float*)d_in[4];
    const float* wq_b   = (const float*)d_in[5];
    const float* wk_w   = (const float*)d_in[6];
    const float* wk_b   = (const float*)d_in[7];
    const float* wv_w   = (const float*)d_in[8];
    const float* wv_b   = (const float*)d_in[9];
    const float* fc_w   = (const float*)d_in[10];
    const float* fc_b   = (const float*)d_in[11];
    float* out = (float*)d_out;

    float *pq, *pk, *pv, *pattn;
    cudaGetSymbolAddress((void**)&pq, g_q);
    cudaGetSymbolAddress((void**)&pk, g_k);
    cudaGetSymbolAddress((void**)&pv, g_v);
    cudaGetSymbolAddress((void**)&pattn, g_attn);

    cudaFuncSetAttribute(attn_tf32,
                         cudaFuncAttributeMaxDynamicSharedMemorySize,
                         ATTN_SMEM_BYTES);

    dim3 ggrid(D_MODEL / 128, M_ROWS / 128);   // (8, 64)
    gemm_tf32<1><<<ggrid, 256>>>(query,  wq_w, wq_b, pq);
    gemm_tf32<1><<<ggrid, 256>>>(key_in, wk_w, wk_b, pk);
    gemm_tf32<2><<<ggrid, 256>>>(value,  wv_w, wv_b, pv);

    dim3 agrid(SEQ / 64, BATCH * N_HEADS);     // (32, 64)
    attn_tf32<<<agrid, 256, ATTN_SMEM_BYTES>>>(mask, pattn);

    gemm_tf32<0><<<ggrid, 256>>>(pattn, fc_w, fc_b, out);
}

// round 3
// speedup vs baseline: 6.3308x; 1.3253x over previous
#include <cuda_runtime.h>
#include <stdint.h>

#define D_MODEL 1024
#define N_HEADS 16
#define HEAD_DIM 64
#define BATCH 4
#define SEQ 2048
#define M_ROWS (BATCH * SEQ)   // 8192

// ---------------------------------------------------------------------------
// Scratch (device globals: no allocation allowed)
// ---------------------------------------------------------------------------
__device__ float g_q[BATCH * N_HEADS * SEQ * HEAD_DIM];    // [B,H,S,Dh]
__device__ float g_k[BATCH * N_HEADS * SEQ * HEAD_DIM];    // [B,H,S,Dh]
__device__ float g_v[BATCH * N_HEADS * SEQ * HEAD_DIM];    // [B,H,Dh,S]  (transposed!)
__device__ float g_attn[M_ROWS * D_MODEL];                 // [B,S,D]

// ---------------------------------------------------------------------------
// tf32 helpers
// ---------------------------------------------------------------------------
__device__ __forceinline__ uint32_t f2tf(float x) {
    uint32_t r;
    asm("cvt.rna.tf32.f32 %0, %1;" : "=r"(r) : "f"(x));
    return r;
}

__device__ __forceinline__ void mma8(float* c, const uint32_t* a, const uint32_t* b) {
    asm volatile(
        "mma.sync.aligned.m16n8k8.row.col.f32.tf32.tf32.f32 "
        "{%0,%1,%2,%3}, {%4,%5,%6,%7}, {%8,%9}, {%0,%1,%2,%3};"
        : "+f"(c[0]), "+f"(c[1]), "+f"(c[2]), "+f"(c[3])
        : "r"(a[0]), "r"(a[1]), "r"(a[2]), "r"(a[3]), "r"(b[0]), "r"(b[1]));
}

// ---------------------------------------------------------------------------
// GEMM: Y = X @ W^T + bias   (X:[8192,1024], W:[1024,1024], both row-major)
// MODE 0: Y row-major; MODE 1: Y=[B,H,S,Dh]; MODE 2: Y=[B,H,Dh,S]
// 128x128 tile, K-chunk 32, 8 warps at 64x32, register double-buffered loads.
// ---------------------------------------------------------------------------
template <int MODE>
__device__ __forceinline__ void put_out(float* __restrict__ Y, int m, int n, float v) {
    if (MODE == 0) {
        Y[(size_t)m * D_MODEL + n] = v;
    } else {
        int b = m >> 11, s = m & 2047, h = n >> 6, dh = n & 63;
        if (MODE == 1)
            Y[(((size_t)(b * N_HEADS + h)) * SEQ + s) * HEAD_DIM + dh] = v;
        else
            Y[(((size_t)(b * N_HEADS + h)) * HEAD_DIM + dh) * SEQ + s] = v;
    }
}

template <int MODE>
__global__ void __launch_bounds__(256) gemm_tf32(
    const float* __restrict__ X, const float* __restrict__ W,
    const float* __restrict__ bias, float* __restrict__ Y)
{
    __shared__ uint32_t As[128][36];   // [m][k] tf32, stride 36 (==4 mod 32)
    __shared__ uint32_t Bs[128][36];   // [n][k]

    const int tid = threadIdx.x;
    const int l = tid & 31;
    const int wid = tid >> 5;
    const int m0 = blockIdx.y << 7;
    const int n0 = blockIdx.x << 7;
    const int wm = (wid >> 2) << 6;    // 0 / 64
    const int wn = (wid & 3) << 5;     // 0 / 32 / 64 / 96

    const int srow = tid >> 3;          // 0..31  (staging row block base)
    const int sq   = (tid & 7) << 2;    // 0..28  (k quad)

    float c[4][4][4];
#pragma unroll
    for (int mt = 0; mt < 4; mt++)
#pragma unroll
        for (int nt = 0; nt < 4; nt++)
#pragma unroll
            for (int i = 0; i < 4; i++) c[mt][nt][i] = 0.0f;

    float4 xr[4], wr[4];
    // prefetch first K-slab
#pragma unroll
    for (int i = 0; i < 4; i++) {
        int row = srow + (i << 5);
        xr[i] = *(const float4*)(X + (size_t)(m0 + row) * D_MODEL + sq);
        wr[i] = *(const float4*)(W + (size_t)(n0 + row) * D_MODEL + sq);
    }

    for (int k0 = 0; k0 < D_MODEL; k0 += 32) {
        // store current slab (convert to tf32)
#pragma unroll
        for (int i = 0; i < 4; i++) {
            int row = srow + (i << 5);
            uint4 ux = {f2tf(xr[i].x), f2tf(xr[i].y), f2tf(xr[i].z), f2tf(xr[i].w)};
            *(uint4*)&As[row][sq] = ux;
            uint4 uw = {f2tf(wr[i].x), f2tf(wr[i].y), f2tf(wr[i].z), f2tf(wr[i].w)};
            *(uint4*)&Bs[row][sq] = uw;
        }
        __syncthreads();

        // prefetch next slab (overlaps with mma)
        if (k0 + 32 < D_MODEL) {
#pragma unroll
            for (int i = 0; i < 4; i++) {
                int row = srow + (i << 5);
                xr[i] = *(const float4*)(X + (size_t)(m0 + row) * D_MODEL + k0 + 32 + sq);
                wr[i] = *(const float4*)(W + (size_t)(n0 + row) * D_MODEL + k0 + 32 + sq);
            }
        }

#pragma unroll
        for (int ks = 0; ks < 4; ks++) {
            int kk = ks << 3;
            uint32_t a[4][4], b[4][2];
#pragma unroll
            for (int mt = 0; mt < 4; mt++) {
                int r = wm + (mt << 4) + (l >> 2);
                a[mt][0] = As[r][kk + (l & 3)];
                a[mt][1] = As[r + 8][kk + (l & 3)];
                a[mt][2] = As[r][kk + (l & 3) + 4];
                a[mt][3] = As[r + 8][kk + (l & 3) + 4];
            }
#pragma unroll
            for (int nt = 0; nt < 4; nt++) {
                int r = wn + (nt << 3) + (l >> 2);
                b[nt][0] = Bs[r][kk + (l & 3)];
                b[nt][1] = Bs[r][kk + (l & 3) + 4];
            }
#pragma unroll
            for (int mt = 0; mt < 4; mt++)
#pragma unroll
                for (int nt = 0; nt < 4; nt++)
                    mma8(c[mt][nt], a[mt], b[nt]);
        }
        __syncthreads();
    }

#pragma unroll
    for (int mt = 0; mt < 4; mt++) {
#pragma unroll
        for (int nt = 0; nt < 4; nt++) {
            int m = m0 + wm + (mt << 4) + (l >> 2);
            int n = n0 + wn + (nt << 3) + ((l & 3) << 1);
            float b0 = bias[n], b1 = bias[n + 1];
            put_out<MODE>(Y, m,     n,     c[mt][nt][0] + b0);
            put_out<MODE>(Y, m,     n + 1, c[mt][nt][1] + b1);
            put_out<MODE>(Y, m + 8, n,     c[mt][nt][2] + b0);
            put_out<MODE>(Y, m + 8, n + 1, c[mt][nt][3] + b1);
        }
    }
}

// ---------------------------------------------------------------------------
// Flash attention, tf32 mma. One CTA per (bh, 64 q-rows); K-chunk 64.
// smem ~68.5KB -> 2 CTAs/SM. Register prefetch of next K/V tile.
// ---------------------------------------------------------------------------
#define ATTN_SMEM_BYTES ((4 * 64 * 68 + 128) * 4)

__global__ void __launch_bounds__(256, 2) attn_tf32(const int* __restrict__ mask,
                                                    float* __restrict__ out)
{
    extern __shared__ char smraw[];
    uint32_t* Qs = (uint32_t*)smraw;          // [64][68]  tf32 (pre-scaled)
    uint32_t* Ks = Qs + 64 * 68;              // [64][68]  tf32
    uint32_t* Vs = Ks + 64 * 68;              // [64][68]  tf32 ([dh][kpos])
    uint32_t* Pu = Vs + 64 * 68;              // [64][68]  fp32 scores -> tf32 probs
    float* s_alpha = (float*)(Pu + 64 * 68);  // [64]
    float* s_linv  = s_alpha + 64;            // [64]

    const int tid = threadIdx.x;
    const int l = tid & 31;
    const int wid = tid >> 5;
    const int bh = blockIdx.y;
    const int b = bh >> 4, h = bh & 15;
    const int q0 = blockIdx.x << 6;

    const float* Q = g_q + (size_t)bh * SEQ * HEAD_DIM + (size_t)q0 * HEAD_DIM;
    const float* K = g_k + (size_t)bh * SEQ * HEAD_DIM;
    const float* V = g_v + (size_t)bh * HEAD_DIM * SEQ;   // [dh][s]

    const int sr = tid >> 4;            // 0..15 (staging row base)
    const int sc = (tid & 15) << 2;     // 0..60

    // stage Q (scaled by 1/sqrt(64))
#pragma unroll
    for (int i = 0; i < 4; i++) {
        int r = sr + (i << 4);
        float4 v = *(const float4*)(Q + r * HEAD_DIM + sc);
        uint4 u = {f2tf(v.x * 0.125f), f2tf(v.y * 0.125f),
                   f2tf(v.z * 0.125f), f2tf(v.w * 0.125f)};
        *(uint4*)&Qs[r * 68 + sc] = u;
    }

    float o[4][4];
#pragma unroll
    for (int nt = 0; nt < 4; nt++)
#pragma unroll
        for (int i = 0; i < 4; i++) o[nt][i] = 0.0f;

    float m_r = -1e30f, l_r = 0.0f;
    const int srw = tid >> 2, ssub = tid & 3;    // softmax: 4 threads/row, 16 cols each
    const int wm = (wid & 3) << 4;               // row offset
    const int wn2 = (wid >> 2) << 5;             // col offset: 0 / 32

    // prefetch first K/V tile into registers
    float4 kr[4], vr[4];
#pragma unroll
    for (int i = 0; i < 4; i++) {
        int r = sr + (i << 4);
        kr[i] = *(const float4*)(K + (size_t)r * HEAD_DIM + sc);
        vr[i] = *(const float4*)(V + (size_t)r * SEQ + sc);
    }

    for (int kt = 0; kt < SEQ / 64; kt++) {
        const int k0 = kt << 6;
        __syncthreads();   // prev iter done reading Ks/Vs/Pu
        // store staged K/V (convert to tf32)
#pragma unroll
        for (int i = 0; i < 4; i++) {
            int r = sr + (i << 4);
            uint4 uk = {f2tf(kr[i].x), f2tf(kr[i].y), f2tf(kr[i].z), f2tf(kr[i].w)};
            *(uint4*)&Ks[r * 68 + sc] = uk;
            uint4 uv = {f2tf(vr[i].x), f2tf(vr[i].y), f2tf(vr[i].z), f2tf(vr[i].w)};
            *(uint4*)&Vs[r * 68 + sc] = uv;
        }
        __syncthreads();

        // prefetch next tile (overlaps QK mma)
        if (kt + 1 < SEQ / 64) {
            const int kn = k0 + 64;
#pragma unroll
            for (int i = 0; i < 4; i++) {
                int r = sr + (i << 4);
                kr[i] = *(const float4*)(K + (size_t)(kn + r) * HEAD_DIM + sc);
                vr[i] = *(const float4*)(V + (size_t)r * SEQ + kn + sc);
            }
        }

        // ---- QK^T: warp computes rows [wm,wm+16) x cols [wn2,wn2+32) ----
        {
            float cs[4][4];
#pragma unroll
            for (int nt = 0; nt < 4; nt++)
#pragma unroll
                for (int i = 0; i < 4; i++) cs[nt][i] = 0.0f;

#pragma unroll
            for (int ks = 0; ks < 8; ks++) {
                int kk = ks << 3;
                uint32_t a[4];
                int r = wm + (l >> 2);
                a[0] = Qs[r * 68 + kk + (l & 3)];
                a[1] = Qs[(r + 8) * 68 + kk + (l & 3)];
                a[2] = Qs[r * 68 + kk + (l & 3) + 4];
                a[3] = Qs[(r + 8) * 68 + kk + (l & 3) + 4];
#pragma unroll
                for (int nt = 0; nt < 4; nt++) {
                    uint32_t bb[2];
                    int rn = wn2 + (nt << 3) + (l >> 2);
                    bb[0] = Ks[rn * 68 + kk + (l & 3)];
                    bb[1] = Ks[rn * 68 + kk + (l & 3) + 4];
                    mma8(cs[nt], a, bb);
                }
            }
#pragma unroll
            for (int nt = 0; nt < 4; nt++) {
                int r = wm + (l >> 2);
                int cc = wn2 + (nt << 3) + ((l & 3) << 1);
                Pu[r * 68 + cc]           = __float_as_uint(cs[nt][0]);
                Pu[r * 68 + cc + 1]       = __float_as_uint(cs[nt][1]);
                Pu[(r + 8) * 68 + cc]     = __float_as_uint(cs[nt][2]);
                Pu[(r + 8) * 68 + cc + 1] = __float_as_uint(cs[nt][3]);
            }
        }
        __syncthreads();

        // ---- masked online softmax: 4 threads per row, 16 cols each ----
        {
            float sv[16];
            const uint32_t* prow = Pu + srw * 68 + (ssub << 4);
            const int* mrow = mask + ((size_t)(b * SEQ + q0 + srw)) * SEQ + k0 + (ssub << 4);
            float mx = m_r;
#pragma unroll
            for (int j = 0; j < 4; j++) {
                uint4 s4 = *(const uint4*)(prow + (j << 2));
                int4 m4 = *(const int4*)(mrow + (j << 2));
                float v0 = m4.x ? __uint_as_float(s4.x) : -1e9f;
                float v1 = m4.y ? __uint_as_float(s4.y) : -1e9f;
                float v2 = m4.z ? __uint_as_float(s4.z) : -1e9f;
                float v3 = m4.w ? __uint_as_float(s4.w) : -1e9f;
                sv[j * 4 + 0] = v0; sv[j * 4 + 1] = v1;
                sv[j * 4 + 2] = v2; sv[j * 4 + 3] = v3;
                mx = fmaxf(mx, fmaxf(fmaxf(v0, v1), fmaxf(v2, v3)));
            }
            mx = fmaxf(mx, __shfl_xor_sync(0xffffffffu, mx, 1));
            mx = fmaxf(mx, __shfl_xor_sync(0xffffffffu, mx, 2));
            float alpha = __expf(m_r - mx);
            float sum = 0.0f;
            uint32_t* pw = Pu + srw * 68 + (ssub << 4);
#pragma unroll
            for (int j = 0; j < 16; j++) {
                float p = __expf(sv[j] - mx);
                sum += p;
                pw[j] = f2tf(p);
            }
            sum += __shfl_xor_sync(0xffffffffu, sum, 1);
            sum += __shfl_xor_sync(0xffffffffu, sum, 2);
            m_r = mx;
            l_r = l_r * alpha + sum;
            if (ssub == 0) s_alpha[srw] = alpha;
        }
        __syncthreads();

        // ---- PV: warp computes rows [wm,wm+16) x dh [wn2,wn2+32) ----
        {
            float a0 = s_alpha[wm + (l >> 2)];
            float a1 = s_alpha[wm + (l >> 2) + 8];
#pragma unroll
            for (int nt = 0; nt < 4; nt++) {
                o[nt][0] *= a0; o[nt][1] *= a0;
                o[nt][2] *= a1; o[nt][3] *= a1;
            }
#pragma unroll
            for (int ks = 0; ks < 8; ks++) {
                int kk = ks << 3;
                uint32_t a[4];
                int r = wm + (l >> 2);
                a[0] = Pu[r * 68 + kk + (l & 3)];
                a[1] = Pu[(r + 8) * 68 + kk + (l & 3)];
                a[2] = Pu[r * 68 + kk + (l & 3) + 4];
                a[3] = Pu[(r + 8) * 68 + kk + (l & 3) + 4];
#pragma unroll
                for (int nt = 0; nt < 4; nt++) {
                    uint32_t bb[2];
                    int rd = wn2 + (nt << 3) + (l >> 2);
                    bb[0] = Vs[rd * 68 + kk + (l & 3)];
                    bb[1] = Vs[rd * 68 + kk + (l & 3) + 4];
                    mma8(o[nt], a, bb);
                }
            }
        }
    }

    if (ssub == 0) s_linv[srw] = 1.0f / l_r;
    __syncthreads();

#pragma unroll
    for (int nt = 0; nt < 4; nt++) {
        int r = wm + (l >> 2);
        int cc = wn2 + (nt << 3) + ((l & 3) << 1);
        float i0 = s_linv[r], i1 = s_linv[r + 8];
        size_t base0 = (size_t)(b * SEQ + q0 + r) * D_MODEL + h * HEAD_DIM + cc;
        size_t base1 = (size_t)(b * SEQ + q0 + r + 8) * D_MODEL + h * HEAD_DIM + cc;
        out[base0]     = o[nt][0] * i0;
        out[base0 + 1] = o[nt][1] * i0;
        out[base1]     = o[nt][2] * i1;
        out[base1 + 1] = o[nt][3] * i1;
    }
}

// ---------------------------------------------------------------------------
// Launch
// ---------------------------------------------------------------------------
extern "C" void kernel_launch(void* const* d_in, const int* in_sizes, int n_in,
                              void* d_out, int out_size)
{
    const float* query  = (const float*)d_in[0];
    const float* key_in = (const float*)d_in[1];
    const float* value  = (const float*)d_in[2];
    const int*   mask   = (const int*)d_in[3];
    const float* wq_w   = (const float*)d_in[4];
    const float* wq_b   = (const float*)d_in[5];
    const float* wk_w   = (const float*)d_in[6];
    const float* wk_b   = (const float*)d_in[7];
    const float* wv_w   = (const float*)d_in[8];
    const float* wv_b   = (const float*)d_in[9];
    const float* fc_w   = (const float*)d_in[10];
    const float* fc_b   = (const float*)d_in[11];
    float* out = (float*)d_out;

    float *pq, *pk, *pv, *pattn;
    cudaGetSymbolAddress((void**)&pq, g_q);
    cudaGetSymbolAddress((void**)&pk, g_k);
    cudaGetSymbolAddress((void**)&pv, g_v);
    cudaGetSymbolAddress((void**)&pattn, g_attn);

    cudaFuncSetAttribute(attn_tf32,
                         cudaFuncAttributeMaxDynamicSharedMemorySize,
                         ATTN_SMEM_BYTES);

    dim3 ggrid(D_MODEL / 128, M_ROWS / 128);   // (8, 64)
    gemm_tf32<1><<<ggrid, 256>>>(query,  wq_w, wq_b, pq);
    gemm_tf32<1><<<ggrid, 256>>>(key_in, wk_w, wk_b, pk);
    gemm_tf32<2><<<ggrid, 256>>>(value,  wv_w, wv_b, pv);

    dim3 agrid(SEQ / 64, BATCH * N_HEADS);     // (32, 64)
    attn_tf32<<<agrid, 256, ATTN_SMEM_BYTES>>>(mask, pattn);

    gemm_tf32<0><<<ggrid, 256>>>(pattn, fc_w, fc_b, out);
}

// round 4
// speedup vs baseline: 6.7568x; 1.0673x over previous
#include <cuda_runtime.h>
#include <stdint.h>

#define D_MODEL 1024
#define N_HEADS 16
#define HEAD_DIM 64
#define BATCH 4
#define SEQ 2048
#define M_ROWS (BATCH * SEQ)   // 8192

__device__ float g_q[BATCH * N_HEADS * SEQ * HEAD_DIM];    // [B,H,S,Dh]
__device__ float g_k[BATCH * N_HEADS * SEQ * HEAD_DIM];    // [B,H,S,Dh]
__device__ float g_v[BATCH * N_HEADS * SEQ * HEAD_DIM];    // [B,H,Dh,S]  (transposed)
__device__ float g_attn[M_ROWS * D_MODEL];                 // [B,S,D]

// ---------------------------------------------------------------------------
// helpers
// ---------------------------------------------------------------------------
__device__ __forceinline__ uint32_t f2tf(float x) {
    uint32_t r;
    asm("cvt.rna.tf32.f32 %0, %1;" : "=r"(r) : "f"(x));
    return r;
}

__device__ __forceinline__ void mma8(float* c, const uint32_t* a, const uint32_t* b) {
    asm volatile(
        "mma.sync.aligned.m16n8k8.row.col.f32.tf32.tf32.f32 "
        "{%0,%1,%2,%3}, {%4,%5,%6,%7}, {%8,%9}, {%0,%1,%2,%3};"
        : "+f"(c[0]), "+f"(c[1]), "+f"(c[2]), "+f"(c[3])
        : "r"(a[0]), "r"(a[1]), "r"(a[2]), "r"(a[3]), "r"(b[0]), "r"(b[1]));
}

__device__ __forceinline__ uint32_t su32(const void* p) {
    return (uint32_t)__cvta_generic_to_shared(p);
}

__device__ __forceinline__ void ldsm4(uint32_t* r, uint32_t addr) {
    asm volatile("ldmatrix.sync.aligned.m8n8.x4.shared.b16 {%0,%1,%2,%3}, [%4];"
        : "=r"(r[0]), "=r"(r[1]), "=r"(r[2]), "=r"(r[3]) : "r"(addr));
}

// ---------------------------------------------------------------------------
// GEMM: Y = X @ W^T + bias. 128x128 tile, K-chunk 32, 8 warps @64x32, LDSM.
// MODE 0: row-major; MODE 1: [B,H,S,Dh]; MODE 2: [B,H,Dh,S]
// ---------------------------------------------------------------------------
template <int MODE>
__device__ __forceinline__ void put_out(float* __restrict__ Y, int m, int n, float v) {
    if (MODE == 0) {
        Y[(size_t)m * D_MODEL + n] = v;
    } else {
        int b = m >> 11, s = m & 2047, h = n >> 6, dh = n & 63;
        if (MODE == 1)
            Y[(((size_t)(b * N_HEADS + h)) * SEQ + s) * HEAD_DIM + dh] = v;
        else
            Y[(((size_t)(b * N_HEADS + h)) * HEAD_DIM + dh) * SEQ + s] = v;
    }
}

template <int MODE>
__global__ void __launch_bounds__(256) gemm_tf32(
    const float* __restrict__ X, const float* __restrict__ W,
    const float* __restrict__ bias, float* __restrict__ Y)
{
    __shared__ __align__(16) uint32_t As[128][36];   // [m][k], 36 stride
    __shared__ __align__(16) uint32_t Bs[128][36];   // [n][k]

    const int tid = threadIdx.x;
    const int l = tid & 31;
    const int wid = tid >> 5;
    const int m0 = blockIdx.y << 7;
    const int n0 = blockIdx.x << 7;
    const int wm = (wid >> 2) << 6;    // 0 / 64
    const int wn = (wid & 3) << 5;     // 0 / 32 / 64 / 96

    const int srow = tid >> 3;
    const int sq   = (tid & 7) << 2;

    // LDSM base addresses (A: 16x8 tile per mt; B: x4 covers an nt pair)
    uint32_t addrA[4], addrB[2];
#pragma unroll
    for (int mt = 0; mt < 4; mt++)
        addrA[mt] = su32(&As[wm + (mt << 4) + (l & 15)][(l >> 4) << 2]);
#pragma unroll
    for (int p = 0; p < 2; p++)
        addrB[p] = su32(&Bs[wn + (p << 4) + (l & 7) + ((l >> 4) << 3)][((l >> 3) & 1) << 2]);

    float c[4][4][4];
#pragma unroll
    for (int mt = 0; mt < 4; mt++)
#pragma unroll
        for (int nt = 0; nt < 4; nt++)
#pragma unroll
            for (int i = 0; i < 4; i++) c[mt][nt][i] = 0.0f;

    float4 xr[4], wr[4];
#pragma unroll
    for (int i = 0; i < 4; i++) {
        int row = srow + (i << 5);
        xr[i] = *(const float4*)(X + (size_t)(m0 + row) * D_MODEL + sq);
        wr[i] = *(const float4*)(W + (size_t)(n0 + row) * D_MODEL + sq);
    }

    for (int k0 = 0; k0 < D_MODEL; k0 += 32) {
#pragma unroll
        for (int i = 0; i < 4; i++) {
            int row = srow + (i << 5);
            uint4 ux = {f2tf(xr[i].x), f2tf(xr[i].y), f2tf(xr[i].z), f2tf(xr[i].w)};
            *(uint4*)&As[row][sq] = ux;
            uint4 uw = {f2tf(wr[i].x), f2tf(wr[i].y), f2tf(wr[i].z), f2tf(wr[i].w)};
            *(uint4*)&Bs[row][sq] = uw;
        }
        __syncthreads();

        if (k0 + 32 < D_MODEL) {
#pragma unroll
            for (int i = 0; i < 4; i++) {
                int row = srow + (i << 5);
                xr[i] = *(const float4*)(X + (size_t)(m0 + row) * D_MODEL + k0 + 32 + sq);
                wr[i] = *(const float4*)(W + (size_t)(n0 + row) * D_MODEL + k0 + 32 + sq);
            }
        }

#pragma unroll
        for (int ks = 0; ks < 4; ks++) {
            const uint32_t koff = ks << 5;   // 8 words = 32 bytes
            uint32_t a[4][4], b[2][4];
#pragma unroll
            for (int mt = 0; mt < 4; mt++) ldsm4(a[mt], addrA[mt] + koff);
#pragma unroll
            for (int p = 0; p < 2; p++) ldsm4(b[p], addrB[p] + koff);
#pragma unroll
            for (int mt = 0; mt < 4; mt++)
#pragma unroll
                for (int nt = 0; nt < 4; nt++)
                    mma8(c[mt][nt], a[mt], &b[nt >> 1][(nt & 1) << 1]);
        }
        __syncthreads();
    }

#pragma unroll
    for (int mt = 0; mt < 4; mt++) {
#pragma unroll
        for (int nt = 0; nt < 4; nt++) {
            int m = m0 + wm + (mt << 4) + (l >> 2);
            int n = n0 + wn + (nt << 3) + ((l & 3) << 1);
            float b0 = bias[n], b1 = bias[n + 1];
            put_out<MODE>(Y, m,     n,     c[mt][nt][0] + b0);
            put_out<MODE>(Y, m,     n + 1, c[mt][nt][1] + b1);
            put_out<MODE>(Y, m + 8, n,     c[mt][nt][2] + b0);
            put_out<MODE>(Y, m + 8, n + 1, c[mt][nt][3] + b1);
        }
    }
}

// ---------------------------------------------------------------------------
// Flash attention, tf32 mma + LDSM fragment loads. K-chunk 64, 2 CTAs/SM.
// ---------------------------------------------------------------------------
#define ATTN_SMEM_BYTES ((4 * 64 * 68 + 128) * 4)

__global__ void __launch_bounds__(256, 2) attn_tf32(const int* __restrict__ mask,
                                                    float* __restrict__ out)
{
    extern __shared__ __align__(16) char smraw[];
    uint32_t* Qs = (uint32_t*)smraw;          // [64][68]  tf32 (pre-scaled)
    uint32_t* Ks = Qs + 64 * 68;              // [64][68]
    uint32_t* Vs = Ks + 64 * 68;              // [64][68]  ([dh][kpos])
    uint32_t* Pu = Vs + 64 * 68;              // [64][68]  scores(f32) -> probs(tf32)
    float* s_alpha = (float*)(Pu + 64 * 68);  // [64]
    float* s_linv  = s_alpha + 64;            // [64]

    const int tid = threadIdx.x;
    const int l = tid & 31;
    const int wid = tid >> 5;
    const int bh = blockIdx.y;
    const int b = bh >> 4, h = bh & 15;
    const int q0 = blockIdx.x << 6;

    const float* Q = g_q + (size_t)bh * SEQ * HEAD_DIM + (size_t)q0 * HEAD_DIM;
    const float* K = g_k + (size_t)bh * SEQ * HEAD_DIM;
    const float* V = g_v + (size_t)bh * HEAD_DIM * SEQ;   // [dh][s]

    const int sr = tid >> 4;            // staging row base
    const int sc = (tid & 15) << 2;

    const int wm = (wid & 3) << 4;      // warp row offset
    const int wn2 = (wid >> 2) << 5;    // warp col offset: 0 / 32

    // LDSM base addresses
    const uint32_t rowA = (wm + (l & 15)) * 68 + ((l >> 4) << 2);
    const uint32_t aQ = su32(Qs) + rowA * 4;
    const uint32_t aP = su32(Pu) + rowA * 4;
    const uint32_t rowB = (wn2 + (l & 7) + ((l >> 4) << 3)) * 68 + (((l >> 3) & 1) << 2);
    const uint32_t bK = su32(Ks) + rowB * 4;
    const uint32_t bV = su32(Vs) + rowB * 4;
    const uint32_t NT_STRIDE = 16 * 68 * 4;  // nt-pair row offset (16 rows)

    // stage Q (scaled by 1/sqrt(64))
#pragma unroll
    for (int i = 0; i < 4; i++) {
        int r = sr + (i << 4);
        float4 v = *(const float4*)(Q + r * HEAD_DIM + sc);
        uint4 u = {f2tf(v.x * 0.125f), f2tf(v.y * 0.125f),
                   f2tf(v.z * 0.125f), f2tf(v.w * 0.125f)};
        *(uint4*)&Qs[r * 68 + sc] = u;
    }

    float o[4][4];
#pragma unroll
    for (int nt = 0; nt < 4; nt++)
#pragma unroll
        for (int i = 0; i < 4; i++) o[nt][i] = 0.0f;

    float m_r = -1e30f, l_r = 0.0f;
    const int srw = tid >> 2, ssub = tid & 3;   // softmax: 4 threads/row, 16 cols each

    float4 kr[4], vr[4];
#pragma unroll
    for (int i = 0; i < 4; i++) {
        int r = sr + (i << 4);
        kr[i] = *(const float4*)(K + (size_t)r * HEAD_DIM + sc);
        vr[i] = *(const float4*)(V + (size_t)r * SEQ + sc);
    }

    for (int kt = 0; kt < SEQ / 64; kt++) {
        const int k0 = kt << 6;
        __syncthreads();
#pragma unroll
        for (int i = 0; i < 4; i++) {
            int r = sr + (i << 4);
            uint4 uk = {f2tf(kr[i].x), f2tf(kr[i].y), f2tf(kr[i].z), f2tf(kr[i].w)};
            *(uint4*)&Ks[r * 68 + sc] = uk;
            uint4 uv = {f2tf(vr[i].x), f2tf(vr[i].y), f2tf(vr[i].z), f2tf(vr[i].w)};
            *(uint4*)&Vs[r * 68 + sc] = uv;
        }
        __syncthreads();

        if (kt + 1 < SEQ / 64) {
            const int kn = k0 + 64;
#pragma unroll
            for (int i = 0; i < 4; i++) {
                int r = sr + (i << 4);
                kr[i] = *(const float4*)(K + (size_t)(kn + r) * HEAD_DIM + sc);
                vr[i] = *(const float4*)(V + (size_t)r * SEQ + kn + sc);
            }
        }

        // ---- QK^T: rows [wm,wm+16) x cols [wn2,wn2+32) ----
        {
            float cs[4][4];
#pragma unroll
            for (int nt = 0; nt < 4; nt++)
#pragma unroll
                for (int i = 0; i < 4; i++) cs[nt][i] = 0.0f;

#pragma unroll
            for (int ks = 0; ks < 8; ks++) {
                const uint32_t koff = ks << 5;
                uint32_t a[4], b0[4], b1[4];
                ldsm4(a, aQ + koff);
                ldsm4(b0, bK + koff);
                ldsm4(b1, bK + NT_STRIDE + koff);
                mma8(cs[0], a, &b0[0]);
                mma8(cs[1], a, &b0[2]);
                mma8(cs[2], a, &b1[0]);
                mma8(cs[3], a, &b1[2]);
            }
#pragma unroll
            for (int nt = 0; nt < 4; nt++) {
                int r = wm + (l >> 2);
                int cc = wn2 + (nt << 3) + ((l & 3) << 1);
                uint2 u0 = {__float_as_uint(cs[nt][0]), __float_as_uint(cs[nt][1])};
                uint2 u1 = {__float_as_uint(cs[nt][2]), __float_as_uint(cs[nt][3])};
                *(uint2*)&Pu[r * 68 + cc] = u0;
                *(uint2*)&Pu[(r + 8) * 68 + cc] = u1;
            }
        }
        __syncthreads();

        // ---- masked online softmax: 4 threads/row, 16 cols each ----
        {
            float sv[16];
            const uint32_t* prow = Pu + srw * 68 + (ssub << 4);
            const int* mrow = mask + ((size_t)(b * SEQ + q0 + srw)) * SEQ + k0 + (ssub << 4);
            float mx = m_r;
#pragma unroll
            for (int j = 0; j < 4; j++) {
                uint4 s4 = *(const uint4*)(prow + (j << 2));
                int4 m4 = *(const int4*)(mrow + (j << 2));
                float v0 = m4.x ? __uint_as_float(s4.x) : -1e9f;
                float v1 = m4.y ? __uint_as_float(s4.y) : -1e9f;
                float v2 = m4.z ? __uint_as_float(s4.z) : -1e9f;
                float v3 = m4.w ? __uint_as_float(s4.w) : -1e9f;
                sv[j * 4 + 0] = v0; sv[j * 4 + 1] = v1;
                sv[j * 4 + 2] = v2; sv[j * 4 + 3] = v3;
                mx = fmaxf(mx, fmaxf(fmaxf(v0, v1), fmaxf(v2, v3)));
            }
            mx = fmaxf(mx, __shfl_xor_sync(0xffffffffu, mx, 1));
            mx = fmaxf(mx, __shfl_xor_sync(0xffffffffu, mx, 2));
            float alpha = __expf(m_r - mx);
            float sum = 0.0f;
            uint32_t* pw = Pu + srw * 68 + (ssub << 4);
#pragma unroll
            for (int j = 0; j < 4; j++) {
                float e0 = __expf(sv[j * 4 + 0] - mx);
                float e1 = __expf(sv[j * 4 + 1] - mx);
                float e2 = __expf(sv[j * 4 + 2] - mx);
                float e3 = __expf(sv[j * 4 + 3] - mx);
                sum += (e0 + e1) + (e2 + e3);
                uint4 u = {f2tf(e0), f2tf(e1), f2tf(e2), f2tf(e3)};
                *(uint4*)(pw + (j << 2)) = u;
            }
            sum += __shfl_xor_sync(0xffffffffu, sum, 1);
            sum += __shfl_xor_sync(0xffffffffu, sum, 2);
            m_r = mx;
            l_r = l_r * alpha + sum;
            if (ssub == 0) s_alpha[srw] = alpha;
        }
        __syncthreads();

        // ---- PV: rows [wm,wm+16) x dh [wn2,wn2+32) ----
        {
            float a0 = s_alpha[wm + (l >> 2)];
            float a1 = s_alpha[wm + (l >> 2) + 8];
#pragma unroll
            for (int nt = 0; nt < 4; nt++) {
                o[nt][0] *= a0; o[nt][1] *= a0;
                o[nt][2] *= a1; o[nt][3] *= a1;
            }
#pragma unroll
            for (int ks = 0; ks < 8; ks++) {
                const uint32_t koff = ks << 5;
                uint32_t a[4], b0[4], b1[4];
                ldsm4(a, aP + koff);
                ldsm4(b0, bV + koff);
                ldsm4(b1, bV + NT_STRIDE + koff);
                mma8(o[0], a, &b0[0]);
                mma8(o[1], a, &b0[2]);
                mma8(o[2], a, &b1[0]);
                mma8(o[3], a, &b1[2]);
            }
        }
    }

    if (ssub == 0) s_linv[srw] = 1.0f / l_r;
    __syncthreads();

#pragma unroll
    for (int nt = 0; nt < 4; nt++) {
        int r = wm + (l >> 2);
        int cc = wn2 + (nt << 3) + ((l & 3) << 1);
        float i0 = s_linv[r], i1 = s_linv[r + 8];
        size_t base0 = (size_t)(b * SEQ + q0 + r) * D_MODEL + h * HEAD_DIM + cc;
        size_t base1 = (size_t)(b * SEQ + q0 + r + 8) * D_MODEL + h * HEAD_DIM + cc;
        out[base0]     = o[nt][0] * i0;
        out[base0 + 1] = o[nt][1] * i0;
        out[base1]     = o[nt][2] * i1;
        out[base1 + 1] = o[nt][3] * i1;
    }
}

// ---------------------------------------------------------------------------
// Launch
// ---------------------------------------------------------------------------
extern "C" void kernel_launch(void* const* d_in, const int* in_sizes, int n_in,
                              void* d_out, int out_size)
{
    const float* query  = (const float*)d_in[0];
    const float* key_in = (const float*)d_in[1];
    const float* value  = (const float*)d_in[2];
    const int*   mask   = (const int*)d_in[3];
    const float* wq_w   = (const float*)d_in[4];
    const float* wq_b   = (const float*)d_in[5];
    const float* wk_w   = (const float*)d_in[6];
    const float* wk_b   = (const float*)d_in[7];
    const float* wv_w   = (const float*)d_in[8];
    const float* wv_b   = (const float*)d_in[9];
    const float* fc_w   = (const float*)d_in[10];
    const float* fc_b   = (const float*)d_in[11];
    float* out = (float*)d_out;

    float *pq, *pk, *pv, *pattn;
    cudaGetSymbolAddress((void**)&pq, g_q);
    cudaGetSymbolAddress((void**)&pk, g_k);
    cudaGetSymbolAddress((void**)&pv, g_v);
    cudaGetSymbolAddress((void**)&pattn, g_attn);

    cudaFuncSetAttribute(attn_tf32,
                         cudaFuncAttributeMaxDynamicSharedMemorySize,
                         ATTN_SMEM_BYTES);

    dim3 ggrid(D_MODEL / 128, M_ROWS / 128);   // (8, 64)
    gemm_tf32<1><<<ggrid, 256>>>(query,  wq_w, wq_b, pq);
    gemm_tf32<1><<<ggrid, 256>>>(key_in, wk_w, wk_b, pk);
    gemm_tf32<2><<<ggrid, 256>>>(value,  wv_w, wv_b, pv);

    dim3 agrid(SEQ / 64, BATCH * N_HEADS);     // (32, 64)
    attn_tf32<<<agrid, 256, ATTN_SMEM_BYTES>>>(mask, pattn);

    gemm_tf32<0><<<ggrid, 256>>>(pattn, fc_w, fc_b, out);
}

// round 5
// speedup vs baseline: 8.3079x; 1.2296x over previous
#include <cuda_runtime.h>
#include <stdint.h>

#define D_MODEL 1024
#define N_HEADS 16
#define HEAD_DIM 64
#define BATCH 4
#define SEQ 2048
#define M_ROWS (BATCH * SEQ)   // 8192
#define QSCALE 0.18033688011112042f   // 0.125 * log2(e)

__device__ float g_q[BATCH * N_HEADS * SEQ * HEAD_DIM];    // [B,H,S,Dh] pre-scaled, tf32-rounded
__device__ float g_k[BATCH * N_HEADS * SEQ * HEAD_DIM];    // [B,H,S,Dh] tf32-rounded
__device__ float g_v[BATCH * N_HEADS * SEQ * HEAD_DIM];    // [B,H,Dh,S] tf32-rounded (transposed)
__device__ float g_attn[M_ROWS * D_MODEL];                 // [B,S,D]
__device__ uint32_t g_mbits[BATCH * SEQ * SEQ / 32];       // bit-packed mask (2MB)

// ---------------------------------------------------------------------------
// helpers
// ---------------------------------------------------------------------------
__device__ __forceinline__ uint32_t f2tf(float x) {
    uint32_t r;
    asm("cvt.rna.tf32.f32 %0, %1;" : "=r"(r) : "f"(x));
    return r;
}

__device__ __forceinline__ void mma8(float* c, const uint32_t* a, const uint32_t* b) {
    asm volatile(
        "mma.sync.aligned.m16n8k8.row.col.f32.tf32.tf32.f32 "
        "{%0,%1,%2,%3}, {%4,%5,%6,%7}, {%8,%9}, {%0,%1,%2,%3};"
        : "+f"(c[0]), "+f"(c[1]), "+f"(c[2]), "+f"(c[3])
        : "r"(a[0]), "r"(a[1]), "r"(a[2]), "r"(a[3]), "r"(b[0]), "r"(b[1]));
}

__device__ __forceinline__ uint32_t su32(const void* p) {
    return (uint32_t)__cvta_generic_to_shared(p);
}

__device__ __forceinline__ void ldsm4(uint32_t* r, uint32_t addr) {
    asm volatile("ldmatrix.sync.aligned.m8n8.x4.shared.b16 {%0,%1,%2,%3}, [%4];"
        : "=r"(r[0]), "=r"(r[1]), "=r"(r[2]), "=r"(r[3]) : "r"(addr));
}

#define CP16(s, g) asm volatile("cp.async.cg.shared.global [%0], [%1], 16;" :: "r"(s), "l"(g))
#define CP_COMMIT() asm volatile("cp.async.commit_group;")
#define CP_WAIT(n)  asm volatile("cp.async.wait_group %0;" :: "n"(n))

// ---------------------------------------------------------------------------
// mask bit-pack: 16.7M int32 -> 2MB bits
// ---------------------------------------------------------------------------
__global__ void __launch_bounds__(256) pack_mask(const int* __restrict__ mask,
                                                 uint32_t* __restrict__ bits)
{
    int t = blockIdx.x * 256 + threadIdx.x;
    uint32_t w = __ballot_sync(0xffffffffu, mask[t] != 0);
    if ((t & 31) == 0) bits[t >> 5] = w;
}

// ---------------------------------------------------------------------------
// GEMM: Y = X @ W^T + bias. 128x128 tile, K-chunk 32, 8 warps @64x32, LDSM.
// MODE 0: row-major fp32; MODE 1: [B,H,S,Dh] tf32-rounded*scale; MODE 2: [B,H,Dh,S]
// ---------------------------------------------------------------------------
template <int MODE>
__device__ __forceinline__ void put_out(float* __restrict__ Y, int m, int n, float v) {
    if (MODE == 0) {
        Y[(size_t)m * D_MODEL + n] = v;
    } else {
        int b = m >> 11, s = m & 2047, h = n >> 6, dh = n & 63;
        if (MODE == 1)
            Y[(((size_t)(b * N_HEADS + h)) * SEQ + s) * HEAD_DIM + dh] = v;
        else
            Y[(((size_t)(b * N_HEADS + h)) * HEAD_DIM + dh) * SEQ + s] = v;
    }
}

template <int MODE>
__global__ void __launch_bounds__(256) gemm_tf32(
    const float* __restrict__ X, const float* __restrict__ W,
    const float* __restrict__ bias, float* __restrict__ Y, float scale)
{
    __shared__ __align__(16) uint32_t As[128][36];
    __shared__ __align__(16) uint32_t Bs[128][36];

    const int tid = threadIdx.x;
    const int l = tid & 31;
    const int wid = tid >> 5;
    const int m0 = blockIdx.y << 7;
    const int n0 = blockIdx.x << 7;
    const int wm = (wid >> 2) << 6;
    const int wn = (wid & 3) << 5;

    const int srow = tid >> 3;
    const int sq   = (tid & 7) << 2;

    uint32_t addrA[4], addrB[2];
#pragma unroll
    for (int mt = 0; mt < 4; mt++)
        addrA[mt] = su32(&As[wm + (mt << 4) + (l & 15)][(l >> 4) << 2]);
#pragma unroll
    for (int p = 0; p < 2; p++)
        addrB[p] = su32(&Bs[wn + (p << 4) + (l & 7) + ((l >> 4) << 3)][((l >> 3) & 1) << 2]);

    float c[4][4][4];
#pragma unroll
    for (int mt = 0; mt < 4; mt++)
#pragma unroll
        for (int nt = 0; nt < 4; nt++)
#pragma unroll
            for (int i = 0; i < 4; i++) c[mt][nt][i] = 0.0f;

    float4 xr[4], wr[4];
#pragma unroll
    for (int i = 0; i < 4; i++) {
        int row = srow + (i << 5);
        xr[i] = *(const float4*)(X + (size_t)(m0 + row) * D_MODEL + sq);
        wr[i] = *(const float4*)(W + (size_t)(n0 + row) * D_MODEL + sq);
    }

    for (int k0 = 0; k0 < D_MODEL; k0 += 32) {
#pragma unroll
        for (int i = 0; i < 4; i++) {
            int row = srow + (i << 5);
            uint4 ux = {f2tf(xr[i].x), f2tf(xr[i].y), f2tf(xr[i].z), f2tf(xr[i].w)};
            *(uint4*)&As[row][sq] = ux;
            uint4 uw = {f2tf(wr[i].x), f2tf(wr[i].y), f2tf(wr[i].z), f2tf(wr[i].w)};
            *(uint4*)&Bs[row][sq] = uw;
        }
        __syncthreads();

        if (k0 + 32 < D_MODEL) {
#pragma unroll
            for (int i = 0; i < 4; i++) {
                int row = srow + (i << 5);
                xr[i] = *(const float4*)(X + (size_t)(m0 + row) * D_MODEL + k0 + 32 + sq);
                wr[i] = *(const float4*)(W + (size_t)(n0 + row) * D_MODEL + k0 + 32 + sq);
            }
        }

#pragma unroll
        for (int ks = 0; ks < 4; ks++) {
            const uint32_t koff = ks << 5;
            uint32_t a[4][4], b[2][4];
#pragma unroll
            for (int mt = 0; mt < 4; mt++) ldsm4(a[mt], addrA[mt] + koff);
#pragma unroll
            for (int p = 0; p < 2; p++) ldsm4(b[p], addrB[p] + koff);
#pragma unroll
            for (int mt = 0; mt < 4; mt++)
#pragma unroll
                for (int nt = 0; nt < 4; nt++)
                    mma8(c[mt][nt], a[mt], &b[nt >> 1][(nt & 1) << 1]);
        }
        __syncthreads();
    }

#pragma unroll
    for (int mt = 0; mt < 4; mt++) {
#pragma unroll
        for (int nt = 0; nt < 4; nt++) {
            int m = m0 + wm + (mt << 4) + (l >> 2);
            int n = n0 + wn + (nt << 3) + ((l & 3) << 1);
            float v00 = c[mt][nt][0] + bias[n];
            float v01 = c[mt][nt][1] + bias[n + 1];
            float v10 = c[mt][nt][2] + bias[n];
            float v11 = c[mt][nt][3] + bias[n + 1];
            if (MODE != 0) {
                v00 = __uint_as_float(f2tf(v00 * scale));
                v01 = __uint_as_float(f2tf(v01 * scale));
                v10 = __uint_as_float(f2tf(v10 * scale));
                v11 = __uint_as_float(f2tf(v11 * scale));
            }
            put_out<MODE>(Y, m,     n,     v00);
            put_out<MODE>(Y, m,     n + 1, v01);
            put_out<MODE>(Y, m + 8, n,     v10);
            put_out<MODE>(Y, m + 8, n + 1, v11);
        }
    }
}

// ---------------------------------------------------------------------------
// Flash attention: 8 warps x (16 rows x full 64-col K-chunk), 128 q-rows/CTA.
// cp.async double-buffered K/V, in-register softmax, in-register P via shfl.
// ---------------------------------------------------------------------------
#define TILE_WORDS (64 * 68)
#define BUF_WORDS  (2 * TILE_WORDS)
#define ATTN_SMEM_BYTES (4 * TILE_WORDS * 4)   // 69632
#define NTILES (SEQ / 64)

__global__ void __launch_bounds__(256, 2) attn_tf32(const uint32_t* __restrict__ mbits,
                                                    float* __restrict__ out)
{
    extern __shared__ __align__(16) uint32_t sm[];
    const int tid = threadIdx.x;
    const int l = tid & 31, wid = tid >> 5;
    const int q = l & 3;
    const int bh = blockIdx.y, b = bh >> 4, h = bh & 15;
    const int q0 = blockIdx.x << 7;
    const int wm = wid << 4;

    const float* Qg = g_q + (size_t)bh * SEQ * HEAD_DIM + (size_t)q0 * HEAD_DIM;
    const float* Kg = g_k + (size_t)bh * SEQ * HEAD_DIM;
    const float* Vg = g_v + (size_t)bh * HEAD_DIM * SEQ;

    const uint32_t smb = su32(sm);

    // ---- stage Q once (128 rows span K0+V0 regions), load fragments to regs
#pragma unroll
    for (int i = 0; i < 8; i++) {
        int idx = tid + (i << 8);
        int r = idx >> 4, c = (idx & 15) << 2;
        float4 v = *(const float4*)(Qg + r * HEAD_DIM + c);
        *(float4*)((char*)sm + ((size_t)(r * 68 + c) << 2)) = v;
    }
    __syncthreads();
    uint32_t qf[8][4];
    {
        uint32_t aQ = smb + (((wm + (l & 15)) * 68 + ((l >> 4) << 2)) << 2);
#pragma unroll
        for (int ks = 0; ks < 8; ks++) ldsm4(qf[ks], aQ + (ks << 5));
    }
    __syncthreads();

    // LDSM B-side base offset (within a tile)
    const uint32_t rowBoff = (((l & 7) + ((l >> 4) << 3)) * 68 + (((l >> 3) & 1) << 2)) << 2;

    // ---- cp.async tile issuer: 64 rows x 64 floats per tile, 4 chunks/thread
    auto issue_tile = [&](int tile, int buf) {
        uint32_t sK = smb + ((buf * BUF_WORDS) << 2);
        uint32_t sV = sK + (TILE_WORDS << 2);
        int k0 = tile << 6;
#pragma unroll
        for (int i = 0; i < 4; i++) {
            int lin = tid + (i << 8);
            int r = lin >> 4, c = (lin & 15) << 2;
            CP16(sK + ((r * 68 + c) << 2), Kg + (size_t)(k0 + r) * HEAD_DIM + c);
            CP16(sV + ((r * 68 + c) << 2), Vg + (size_t)r * SEQ + k0 + c);
        }
        CP_COMMIT();
    };

    float o[8][4];
#pragma unroll
    for (int nt = 0; nt < 8; nt++)
#pragma unroll
        for (int i = 0; i < 4; i++) o[nt][i] = 0.0f;

    float m0 = -1e30f, m1 = -1e30f, l0 = 0.0f, l1 = 0.0f;
    const size_t rowg = (size_t)(b * SEQ + q0 + wm + (l >> 2));

    issue_tile(0, 0);

    for (int kt = 0; kt < NTILES; kt++) {
        const int cur = kt & 1;
        if (kt + 1 < NTILES) { issue_tile(kt + 1, cur ^ 1); CP_WAIT(1); }
        else                 { CP_WAIT(0); }
        __syncthreads();

        const uint32_t bK = smb + ((cur * BUF_WORDS) << 2) + rowBoff;
        const uint32_t bV = bK + (TILE_WORDS << 2);

        // ---- QK^T: 16 rows x 64 cols per warp ----
        float cs[8][4];
#pragma unroll
        for (int nt = 0; nt < 8; nt++)
#pragma unroll
            for (int i = 0; i < 4; i++) cs[nt][i] = 0.0f;

#pragma unroll
        for (int ks = 0; ks < 8; ks++) {
#pragma unroll
            for (int pr = 0; pr < 4; pr++) {
                uint32_t bb[4];
                ldsm4(bb, bK + pr * (16 * 68 * 4) + (ks << 5));
                mma8(cs[2 * pr],     qf[ks], &bb[0]);
                mma8(cs[2 * pr + 1], qf[ks], &bb[2]);
            }
        }

        // ---- masked online softmax, fully in registers ----
        {
            const uint2 wa = *(const uint2*)(mbits + rowg * 64 + (kt << 1));
            const uint2 wb = *(const uint2*)(mbits + (rowg + 8) * 64 + (kt << 1));
            float mx0 = m0, mx1 = m1;
#pragma unroll
            for (int nt = 0; nt < 8; nt++) {
                int j = ((nt & 3) << 3) + (q << 1);
                uint32_t w0 = (nt < 4) ? wa.x : wa.y;
                uint32_t w1 = (nt < 4) ? wb.x : wb.y;
                cs[nt][0] = ((w0 >> j) & 1u)       ? cs[nt][0] : -1e9f;
                cs[nt][1] = ((w0 >> (j + 1)) & 1u) ? cs[nt][1] : -1e9f;
                cs[nt][2] = ((w1 >> j) & 1u)       ? cs[nt][2] : -1e9f;
                cs[nt][3] = ((w1 >> (j + 1)) & 1u) ? cs[nt][3] : -1e9f;
                mx0 = fmaxf(mx0, fmaxf(cs[nt][0], cs[nt][1]));
                mx1 = fmaxf(mx1, fmaxf(cs[nt][2], cs[nt][3]));
            }
            mx0 = fmaxf(mx0, __shfl_xor_sync(0xffffffffu, mx0, 1));
            mx0 = fmaxf(mx0, __shfl_xor_sync(0xffffffffu, mx0, 2));
            mx1 = fmaxf(mx1, __shfl_xor_sync(0xffffffffu, mx1, 1));
            mx1 = fmaxf(mx1, __shfl_xor_sync(0xffffffffu, mx1, 2));
            float alpha0 = exp2f(m0 - mx0), alpha1 = exp2f(m1 - mx1);
            m0 = mx0; m1 = mx1;
            float sum0 = 0.0f, sum1 = 0.0f;
#pragma unroll
            for (int nt = 0; nt < 8; nt++) {
                float e0 = exp2f(cs[nt][0] - mx0);
                float e1 = exp2f(cs[nt][1] - mx0);
                float e2 = exp2f(cs[nt][2] - mx1);
                float e3 = exp2f(cs[nt][3] - mx1);
                sum0 += e0 + e1; sum1 += e2 + e3;
                cs[nt][0] = __uint_as_float(f2tf(e0));
                cs[nt][1] = __uint_as_float(f2tf(e1));
                cs[nt][2] = __uint_as_float(f2tf(e2));
                cs[nt][3] = __uint_as_float(f2tf(e3));
            }
            sum0 += __shfl_xor_sync(0xffffffffu, sum0, 1);
            sum0 += __shfl_xor_sync(0xffffffffu, sum0, 2);
            sum1 += __shfl_xor_sync(0xffffffffu, sum1, 1);
            sum1 += __shfl_xor_sync(0xffffffffu, sum1, 2);
            l0 = l0 * alpha0 + sum0;
            l1 = l1 * alpha1 + sum1;
#pragma unroll
            for (int nt = 0; nt < 8; nt++) {
                o[nt][0] *= alpha0; o[nt][1] *= alpha0;
                o[nt][2] *= alpha1; o[nt][3] *= alpha1;
            }
        }

        // ---- PV: P fragments built via quad shuffles ----
        const int src1 = q >> 1;
        const int src2 = 2 + (q >> 1);
        const bool odd = (q & 1);
#pragma unroll
        for (int ks = 0; ks < 8; ks++) {
            float v0 = __shfl_sync(0xffffffffu, cs[ks][0], src1, 4);
            float v1 = __shfl_sync(0xffffffffu, cs[ks][1], src1, 4);
            float v2 = __shfl_sync(0xffffffffu, cs[ks][2], src1, 4);
            float v3 = __shfl_sync(0xffffffffu, cs[ks][3], src1, 4);
            float u0 = __shfl_sync(0xffffffffu, cs[ks][0], src2, 4);
            float u1 = __shfl_sync(0xffffffffu, cs[ks][1], src2, 4);
            float u2 = __shfl_sync(0xffffffffu, cs[ks][2], src2, 4);
            float u3 = __shfl_sync(0xffffffffu, cs[ks][3], src2, 4);
            uint32_t a[4];
            a[0] = __float_as_uint(odd ? v1 : v0);
            a[1] = __float_as_uint(odd ? v3 : v2);
            a[2] = __float_as_uint(odd ? u1 : u0);
            a[3] = __float_as_uint(odd ? u3 : u2);
#pragma unroll
            for (int pr = 0; pr < 4; pr++) {
                uint32_t bb[4];
                ldsm4(bb, bV + pr * (16 * 68 * 4) + (ks << 5));
                mma8(o[2 * pr],     a, &bb[0]);
                mma8(o[2 * pr + 1], a, &bb[2]);
            }
        }
        __syncthreads();
    }

    // ---- epilogue ----
    float inv0 = 1.0f / l0, inv1 = 1.0f / l1;
    float* o0 = out + (size_t)(b * SEQ + q0 + wm + (l >> 2)) * D_MODEL + h * HEAD_DIM + (q << 1);
    float* o1 = o0 + (size_t)8 * D_MODEL;
#pragma unroll
    for (int nt = 0; nt < 8; nt++) {
        float2 r0 = {o[nt][0] * inv0, o[nt][1] * inv0};
        float2 r1 = {o[nt][2] * inv1, o[nt][3] * inv1};
        *(float2*)(o0 + (nt << 3)) = r0;
        *(float2*)(o1 + (nt << 3)) = r1;
    }
}

// ---------------------------------------------------------------------------
// Launch
// ---------------------------------------------------------------------------
extern "C" void kernel_launch(void* const* d_in, const int* in_sizes, int n_in,
                              void* d_out, int out_size)
{
    const float* query  = (const float*)d_in[0];
    const float* key_in = (const float*)d_in[1];
    const float* value  = (const float*)d_in[2];
    const int*   mask   = (const int*)d_in[3];
    const float* wq_w   = (const float*)d_in[4];
    const float* wq_b   = (const float*)d_in[5];
    const float* wk_w   = (const float*)d_in[6];
    const float* wk_b   = (const float*)d_in[7];
    const float* wv_w   = (const float*)d_in[8];
    const float* wv_b   = (const float*)d_in[9];
    const float* fc_w   = (const float*)d_in[10];
    const float* fc_b   = (const float*)d_in[11];
    float* out = (float*)d_out;

    float *pq, *pk, *pv, *pattn;
    uint32_t* pmb;
    cudaGetSymbolAddress((void**)&pq, g_q);
    cudaGetSymbolAddress((void**)&pk, g_k);
    cudaGetSymbolAddress((void**)&pv, g_v);
    cudaGetSymbolAddress((void**)&pattn, g_attn);
    cudaGetSymbolAddress((void**)&pmb, g_mbits);

    cudaFuncSetAttribute(attn_tf32,
                         cudaFuncAttributeMaxDynamicSharedMemorySize,
                         ATTN_SMEM_BYTES);

    pack_mask<<<BATCH * SEQ * SEQ / 32 / 256 * 32, 256>>>(mask, pmb);

    dim3 ggrid(D_MODEL / 128, M_ROWS / 128);   // (8, 64)
    gemm_tf32<1><<<ggrid, 256>>>(query,  wq_w, wq_b, pq, QSCALE);
    gemm_tf32<1><<<ggrid, 256>>>(key_in, wk_w, wk_b, pk, 1.0f);
    gemm_tf32<2><<<ggrid, 256>>>(value,  wv_w, wv_b, pv, 1.0f);

    dim3 agrid(SEQ / 128, BATCH * N_HEADS);    // (16, 64)
    attn_tf32<<<agrid, 256, ATTN_SMEM_BYTES>>>(pmb, pattn);

    gemm_tf32<0><<<ggrid, 256>>>(pattn, fc_w, fc_b, out, 1.0f);
}

// round 6
// speedup vs baseline: 8.7667x; 1.0552x over previous
#include <cuda_runtime.h>
#include <stdint.h>

#define D_MODEL 1024
#define N_HEADS 16
#define HEAD_DIM 64
#define BATCH 4
#define SEQ 2048
#define M_ROWS (BATCH * SEQ)   // 8192
#define QSCALE 0.18033688011112042f   // 0.125 * log2(e)

__device__ float g_q[BATCH * N_HEADS * SEQ * HEAD_DIM];    // [B,H,S,Dh] pre-scaled, tf32-rounded
__device__ float g_k[BATCH * N_HEADS * SEQ * HEAD_DIM];    // [B,H,S,Dh] tf32-rounded
__device__ float g_v[BATCH * N_HEADS * SEQ * HEAD_DIM];    // [B,H,Dh,S] tf32-rounded (transposed)
__device__ float g_attn[M_ROWS * D_MODEL];                 // [B,S,D]
__device__ uint32_t g_mbits[BATCH * SEQ * SEQ / 32];       // bit-packed mask (2MB)

// ---------------------------------------------------------------------------
// helpers
// ---------------------------------------------------------------------------
__device__ __forceinline__ uint32_t f2tf(float x) {
    uint32_t r;
    asm("cvt.rna.tf32.f32 %0, %1;" : "=r"(r) : "f"(x));
    return r;
}

__device__ __forceinline__ void mma8(float* c, const uint32_t* a, const uint32_t* b) {
    asm volatile(
        "mma.sync.aligned.m16n8k8.row.col.f32.tf32.tf32.f32 "
        "{%0,%1,%2,%3}, {%4,%5,%6,%7}, {%8,%9}, {%0,%1,%2,%3};"
        : "+f"(c[0]), "+f"(c[1]), "+f"(c[2]), "+f"(c[3])
        : "r"(a[0]), "r"(a[1]), "r"(a[2]), "r"(a[3]), "r"(b[0]), "r"(b[1]));
}

__device__ __forceinline__ uint32_t su32(const void* p) {
    return (uint32_t)__cvta_generic_to_shared(p);
}

__device__ __forceinline__ void ldsm4(uint32_t* r, uint32_t addr) {
    asm volatile("ldmatrix.sync.aligned.m8n8.x4.shared.b16 {%0,%1,%2,%3}, [%4];"
        : "=r"(r[0]), "=r"(r[1]), "=r"(r[2]), "=r"(r[3]) : "r"(addr));
}

#define CP16(s, g) asm volatile("cp.async.cg.shared.global [%0], [%1], 16;" :: "r"(s), "l"(g))
#define CP_COMMIT() asm volatile("cp.async.commit_group;")
#define CP_WAIT(n)  asm volatile("cp.async.wait_group %0;" :: "n"(n))

// ---------------------------------------------------------------------------
// mask bit-pack
// ---------------------------------------------------------------------------
__global__ void __launch_bounds__(256) pack_mask(const int* __restrict__ mask,
                                                 uint32_t* __restrict__ bits)
{
    int t = blockIdx.x * 256 + threadIdx.x;
    uint32_t w = __ballot_sync(0xffffffffu, mask[t] != 0);
    if ((t & 31) == 0) bits[t >> 5] = w;
}

// ---------------------------------------------------------------------------
// GEMM: Y = X @ W^T + bias. 128x128 tile, K-chunk 32, 3-stage cp.async,
// 8 warps @64x32, LDSM, raw-fp32-as-tf32 operands (HW truncation).
// MODE 0: row-major fp32; MODE 1: [B,H,S,Dh] tf32-RN*scale; MODE 2: [B,H,Dh,S]
// ---------------------------------------------------------------------------
#define GSTAGE_WORDS (2 * 128 * 36)            // A+B per stage
#define GEMM_SMEM_BYTES (3 * GSTAGE_WORDS * 4) // 110592

template <int MODE>
__device__ __forceinline__ void put_out(float* __restrict__ Y, int m, int n, float v) {
    if (MODE == 0) {
        Y[(size_t)m * D_MODEL + n] = v;
    } else {
        int b = m >> 11, s = m & 2047, h = n >> 6, dh = n & 63;
        if (MODE == 1)
            Y[(((size_t)(b * N_HEADS + h)) * SEQ + s) * HEAD_DIM + dh] = v;
        else
            Y[(((size_t)(b * N_HEADS + h)) * HEAD_DIM + dh) * SEQ + s] = v;
    }
}

template <int MODE>
__global__ void __launch_bounds__(256, 2) gemm_tf32(
    const float* __restrict__ X, const float* __restrict__ W,
    const float* __restrict__ bias, float* __restrict__ Y, float scale)
{
    extern __shared__ __align__(16) uint32_t gsm[];

    const int tid = threadIdx.x;
    const int l = tid & 31;
    const int wid = tid >> 5;
    const int m0 = blockIdx.y << 7;
    const int n0 = blockIdx.x << 7;
    const int wm = (wid >> 2) << 6;
    const int wn = (wid & 3) << 5;

    const int srow = tid >> 3;          // 0..31
    const int sq   = (tid & 7) << 2;    // 0..28
    const uint32_t smb = su32(gsm);

    // fragment offsets relative to stage base (bytes)
    uint32_t offA[4];
#pragma unroll
    for (int mt = 0; mt < 4; mt++)
        offA[mt] = ((wm + (mt << 4) + (l & 15)) * 36 + ((l >> 4) << 2)) << 2;
    uint32_t offB[2];
#pragma unroll
    for (int p = 0; p < 2; p++)
        offB[p] = ((128 + wn + (p << 4) + (l & 7) + ((l >> 4) << 3)) * 36 +
                   (((l >> 3) & 1) << 2)) << 2;

    float c[4][4][4];
#pragma unroll
    for (int mt = 0; mt < 4; mt++)
#pragma unroll
        for (int nt = 0; nt < 4; nt++)
#pragma unroll
            for (int i = 0; i < 4; i++) c[mt][nt][i] = 0.0f;

    auto issue = [&](int k0, int s) {
        uint32_t base = smb + (uint32_t)s * (GSTAGE_WORDS << 2);
#pragma unroll
        for (int i = 0; i < 4; i++) {
            int row = srow + (i << 5);
            CP16(base + ((row * 36 + sq) << 2),
                 X + (size_t)(m0 + row) * D_MODEL + k0 + sq);
            CP16(base + (((128 + row) * 36 + sq) << 2),
                 W + (size_t)(n0 + row) * D_MODEL + k0 + sq);
        }
        CP_COMMIT();
    };

    issue(0, 0);
    issue(32, 1);

    const int NCHUNK = D_MODEL / 32;   // 32
    for (int kc = 0; kc < NCHUNK; kc++) {
        if (kc + 1 < NCHUNK) { CP_WAIT(1); } else { CP_WAIT(0); }
        __syncthreads();
        if (kc + 2 < NCHUNK) issue((kc + 2) << 5, (kc + 2) % 3);

        const uint32_t sb = smb + (uint32_t)(kc % 3) * (GSTAGE_WORDS << 2);
#pragma unroll
        for (int ks = 0; ks < 4; ks++) {
            const uint32_t koff = ks << 5;
            uint32_t a[4][4], b[2][4];
#pragma unroll
            for (int mt = 0; mt < 4; mt++) ldsm4(a[mt], sb + offA[mt] + koff);
#pragma unroll
            for (int p = 0; p < 2; p++) ldsm4(b[p], sb + offB[p] + koff);
#pragma unroll
            for (int mt = 0; mt < 4; mt++)
#pragma unroll
                for (int nt = 0; nt < 4; nt++)
                    mma8(c[mt][nt], a[mt], &b[nt >> 1][(nt & 1) << 1]);
        }
        __syncthreads();
    }

#pragma unroll
    for (int mt = 0; mt < 4; mt++) {
#pragma unroll
        for (int nt = 0; nt < 4; nt++) {
            int m = m0 + wm + (mt << 4) + (l >> 2);
            int n = n0 + wn + (nt << 3) + ((l & 3) << 1);
            float v00 = c[mt][nt][0] + bias[n];
            float v01 = c[mt][nt][1] + bias[n + 1];
            float v10 = c[mt][nt][2] + bias[n];
            float v11 = c[mt][nt][3] + bias[n + 1];
            if (MODE != 0) {
                v00 = __uint_as_float(f2tf(v00 * scale));
                v01 = __uint_as_float(f2tf(v01 * scale));
                v10 = __uint_as_float(f2tf(v10 * scale));
                v11 = __uint_as_float(f2tf(v11 * scale));
            }
            put_out<MODE>(Y, m,     n,     v00);
            put_out<MODE>(Y, m,     n + 1, v01);
            put_out<MODE>(Y, m + 8, n,     v10);
            put_out<MODE>(Y, m + 8, n + 1, v11);
        }
    }
}

// ---------------------------------------------------------------------------
// Flash attention: 8 warps x (16 rows x full 64-col K-chunk), 128 q-rows/CTA.
// cp.async double-buffered K/V, in-register softmax, in-register P via shfl.
// ---------------------------------------------------------------------------
#define TILE_WORDS (64 * 68)
#define BUF_WORDS  (2 * TILE_WORDS)
#define ATTN_SMEM_BYTES (4 * TILE_WORDS * 4)   // 69632
#define NTILES (SEQ / 64)

__global__ void __launch_bounds__(256, 2) attn_tf32(const uint32_t* __restrict__ mbits,
                                                    float* __restrict__ out)
{
    extern __shared__ __align__(16) uint32_t sm[];
    const int tid = threadIdx.x;
    const int l = tid & 31, wid = tid >> 5;
    const int q = l & 3;
    const int bh = blockIdx.y, b = bh >> 4, h = bh & 15;
    const int q0 = blockIdx.x << 7;
    const int wm = wid << 4;

    const float* Qg = g_q + (size_t)bh * SEQ * HEAD_DIM + (size_t)q0 * HEAD_DIM;
    const float* Kg = g_k + (size_t)bh * SEQ * HEAD_DIM;
    const float* Vg = g_v + (size_t)bh * HEAD_DIM * SEQ;

    const uint32_t smb = su32(sm);

    // stage Q once, load fragments to regs
#pragma unroll
    for (int i = 0; i < 8; i++) {
        int idx = tid + (i << 8);
        int r = idx >> 4, c = (idx & 15) << 2;
        float4 v = *(const float4*)(Qg + r * HEAD_DIM + c);
        *(float4*)((char*)sm + ((size_t)(r * 68 + c) << 2)) = v;
    }
    __syncthreads();
    uint32_t qf[8][4];
    {
        uint32_t aQ = smb + (((wm + (l & 15)) * 68 + ((l >> 4) << 2)) << 2);
#pragma unroll
        for (int ks = 0; ks < 8; ks++) ldsm4(qf[ks], aQ + (ks << 5));
    }
    __syncthreads();

    const uint32_t rowBoff = (((l & 7) + ((l >> 4) << 3)) * 68 + (((l >> 3) & 1) << 2)) << 2;

    auto issue_tile = [&](int tile, int buf) {
        uint32_t sK = smb + ((buf * BUF_WORDS) << 2);
        uint32_t sV = sK + (TILE_WORDS << 2);
        int k0 = tile << 6;
#pragma unroll
        for (int i = 0; i < 4; i++) {
            int lin = tid + (i << 8);
            int r = lin >> 4, c = (lin & 15) << 2;
            CP16(sK + ((r * 68 + c) << 2), Kg + (size_t)(k0 + r) * HEAD_DIM + c);
            CP16(sV + ((r * 68 + c) << 2), Vg + (size_t)r * SEQ + k0 + c);
        }
        CP_COMMIT();
    };

    float o[8][4];
#pragma unroll
    for (int nt = 0; nt < 8; nt++)
#pragma unroll
        for (int i = 0; i < 4; i++) o[nt][i] = 0.0f;

    float m0 = -1e30f, m1 = -1e30f, l0 = 0.0f, l1 = 0.0f;
    const size_t rowg = (size_t)(b * SEQ + q0 + wm + (l >> 2));

    issue_tile(0, 0);

    for (int kt = 0; kt < NTILES; kt++) {
        const int cur = kt & 1;
        if (kt + 1 < NTILES) { issue_tile(kt + 1, cur ^ 1); CP_WAIT(1); }
        else                 { CP_WAIT(0); }
        __syncthreads();

        const uint32_t bK = smb + ((cur * BUF_WORDS) << 2) + rowBoff;
        const uint32_t bV = bK + (TILE_WORDS << 2);

        // ---- QK^T ----
        float cs[8][4];
#pragma unroll
        for (int nt = 0; nt < 8; nt++)
#pragma unroll
            for (int i = 0; i < 4; i++) cs[nt][i] = 0.0f;

#pragma unroll
        for (int ks = 0; ks < 8; ks++) {
#pragma unroll
            for (int pr = 0; pr < 4; pr++) {
                uint32_t bb[4];
                ldsm4(bb, bK + pr * (16 * 68 * 4) + (ks << 5));
                mma8(cs[2 * pr],     qf[ks], &bb[0]);
                mma8(cs[2 * pr + 1], qf[ks], &bb[2]);
            }
        }

        // ---- masked online softmax (registers) ----
        {
            const uint2 wa = *(const uint2*)(mbits + rowg * 64 + (kt << 1));
            const uint2 wb = *(const uint2*)(mbits + (rowg + 8) * 64 + (kt << 1));
            float mx0 = m0, mx1 = m1;
#pragma unroll
            for (int nt = 0; nt < 8; nt++) {
                int j = ((nt & 3) << 3) + (q << 1);
                uint32_t w0 = (nt < 4) ? wa.x : wa.y;
                uint32_t w1 = (nt < 4) ? wb.x : wb.y;
                cs[nt][0] = ((w0 >> j) & 1u)       ? cs[nt][0] : -1e9f;
                cs[nt][1] = ((w0 >> (j + 1)) & 1u) ? cs[nt][1] : -1e9f;
                cs[nt][2] = ((w1 >> j) & 1u)       ? cs[nt][2] : -1e9f;
                cs[nt][3] = ((w1 >> (j + 1)) & 1u) ? cs[nt][3] : -1e9f;
                mx0 = fmaxf(mx0, fmaxf(cs[nt][0], cs[nt][1]));
                mx1 = fmaxf(mx1, fmaxf(cs[nt][2], cs[nt][3]));
            }
            mx0 = fmaxf(mx0, __shfl_xor_sync(0xffffffffu, mx0, 1));
            mx0 = fmaxf(mx0, __shfl_xor_sync(0xffffffffu, mx0, 2));
            mx1 = fmaxf(mx1, __shfl_xor_sync(0xffffffffu, mx1, 1));
            mx1 = fmaxf(mx1, __shfl_xor_sync(0xffffffffu, mx1, 2));
            float alpha0 = exp2f(m0 - mx0), alpha1 = exp2f(m1 - mx1);
            m0 = mx0; m1 = mx1;
            float sum0 = 0.0f, sum1 = 0.0f;
#pragma unroll
            for (int nt = 0; nt < 8; nt++) {
                float r0 = __uint_as_float(f2tf(exp2f(cs[nt][0] - mx0)));
                float r1 = __uint_as_float(f2tf(exp2f(cs[nt][1] - mx0)));
                float r2 = __uint_as_float(f2tf(exp2f(cs[nt][2] - mx1)));
                float r3 = __uint_as_float(f2tf(exp2f(cs[nt][3] - mx1)));
                sum0 += r0 + r1; sum1 += r2 + r3;
                cs[nt][0] = r0; cs[nt][1] = r1; cs[nt][2] = r2; cs[nt][3] = r3;
            }
            sum0 += __shfl_xor_sync(0xffffffffu, sum0, 1);
            sum0 += __shfl_xor_sync(0xffffffffu, sum0, 2);
            sum1 += __shfl_xor_sync(0xffffffffu, sum1, 1);
            sum1 += __shfl_xor_sync(0xffffffffu, sum1, 2);
            l0 = l0 * alpha0 + sum0;
            l1 = l1 * alpha1 + sum1;
#pragma unroll
            for (int nt = 0; nt < 8; nt++) {
                o[nt][0] *= alpha0; o[nt][1] *= alpha0;
                o[nt][2] *= alpha1; o[nt][3] *= alpha1;
            }
        }

        // ---- PV: P fragments via quad shuffles ----
        const int src1 = q >> 1;
        const int src2 = 2 + (q >> 1);
        const bool odd = (q & 1);
#pragma unroll
        for (int ks = 0; ks < 8; ks++) {
            float v0 = __shfl_sync(0xffffffffu, cs[ks][0], src1, 4);
            float v1 = __shfl_sync(0xffffffffu, cs[ks][1], src1, 4);
            float v2 = __shfl_sync(0xffffffffu, cs[ks][2], src1, 4);
            float v3 = __shfl_sync(0xffffffffu, cs[ks][3], src1, 4);
            float u0 = __shfl_sync(0xffffffffu, cs[ks][0], src2, 4);
            float u1 = __shfl_sync(0xffffffffu, cs[ks][1], src2, 4);
            float u2 = __shfl_sync(0xffffffffu, cs[ks][2], src2, 4);
            float u3 = __shfl_sync(0xffffffffu, cs[ks][3], src2, 4);
            uint32_t a[4];
            a[0] = __float_as_uint(odd ? v1 : v0);
            a[1] = __float_as_uint(odd ? v3 : v2);
            a[2] = __float_as_uint(odd ? u1 : u0);
            a[3] = __float_as_uint(odd ? u3 : u2);
#pragma unroll
            for (int pr = 0; pr < 4; pr++) {
                uint32_t bb[4];
                ldsm4(bb, bV + pr * (16 * 68 * 4) + (ks << 5));
                mma8(o[2 * pr],     a, &bb[0]);
                mma8(o[2 * pr + 1], a, &bb[2]);
            }
        }
        __syncthreads();
    }

    float inv0 = 1.0f / l0, inv1 = 1.0f / l1;
    float* o0 = out + (size_t)(b * SEQ + q0 + wm + (l >> 2)) * D_MODEL + h * HEAD_DIM + (q << 1);
    float* o1 = o0 + (size_t)8 * D_MODEL;
#pragma unroll
    for (int nt = 0; nt < 8; nt++) {
        float2 r0 = {o[nt][0] * inv0, o[nt][1] * inv0};
        float2 r1 = {o[nt][2] * inv1, o[nt][3] * inv1};
        *(float2*)(o0 + (nt << 3)) = r0;
        *(float2*)(o1 + (nt << 3)) = r1;
    }
}

// ---------------------------------------------------------------------------
// Launch
// ---------------------------------------------------------------------------
extern "C" void kernel_launch(void* const* d_in, const int* in_sizes, int n_in,
                              void* d_out, int out_size)
{
    const float* query  = (const float*)d_in[0];
    const float* key_in = (const float*)d_in[1];
    const float* value  = (const float*)d_in[2];
    const int*   mask   = (const int*)d_in[3];
    const float* wq_w   = (const float*)d_in[4];
    const float* wq_b   = (const float*)d_in[5];
    const float* wk_w   = (const float*)d_in[6];
    const float* wk_b   = (const float*)d_in[7];
    const float* wv_w   = (const float*)d_in[8];
    const float* wv_b   = (const float*)d_in[9];
    const float* fc_w   = (const float*)d_in[10];
    const float* fc_b   = (const float*)d_in[11];
    float* out = (float*)d_out;

    float *pq, *pk, *pv, *pattn;
    uint32_t* pmb;
    cudaGetSymbolAddress((void**)&pq, g_q);
    cudaGetSymbolAddress((void**)&pk, g_k);
    cudaGetSymbolAddress((void**)&pv, g_v);
    cudaGetSymbolAddress((void**)&pattn, g_attn);
    cudaGetSymbolAddress((void**)&pmb, g_mbits);

    cudaFuncSetAttribute(attn_tf32,
                         cudaFuncAttributeMaxDynamicSharedMemorySize,
                         ATTN_SMEM_BYTES);
    cudaFuncSetAttribute(gemm_tf32<0>,
                         cudaFuncAttributeMaxDynamicSharedMemorySize,
                         GEMM_SMEM_BYTES);
    cudaFuncSetAttribute(gemm_tf32<1>,
                         cudaFuncAttributeMaxDynamicSharedMemorySize,
                         GEMM_SMEM_BYTES);
    cudaFuncSetAttribute(gemm_tf32<2>,
                         cudaFuncAttributeMaxDynamicSharedMemorySize,
                         GEMM_SMEM_BYTES);

    pack_mask<<<BATCH * SEQ * SEQ / 32 / 256 * 32, 256>>>(mask, pmb);

    dim3 ggrid(D_MODEL / 128, M_ROWS / 128);   // (8, 64)
    gemm_tf32<1><<<ggrid, 256, GEMM_SMEM_BYTES>>>(query,  wq_w, wq_b, pq, QSCALE);
    gemm_tf32<1><<<ggrid, 256, GEMM_SMEM_BYTES>>>(key_in, wk_w, wk_b, pk, 1.0f);
    gemm_tf32<2><<<ggrid, 256, GEMM_SMEM_BYTES>>>(value,  wv_w, wv_b, pv, 1.0f);

    dim3 agrid(SEQ / 128, BATCH * N_HEADS);    // (16, 64)
    attn_tf32<<<agrid, 256, ATTN_SMEM_BYTES>>>(pmb, pattn);

    gemm_tf32<0><<<ggrid, 256, GEMM_SMEM_BYTES>>>(pattn, fc_w, fc_b, out, 1.0f);
}